// round 6
// baseline (speedup 1.0000x reference)
#include <cuda_runtime.h>
#include <cuda_bf16.h>
#include <math.h>

#define BB 2
#define NN 8192
#define KK 30
#define NODES (BB*NN)
#define DIM 148

// ---------------- scratch (static device globals; no allocation) ----------------
__device__ float g_vhV[NODES * 96];    // per-node: Wh1[0:16]^T applied to vV -> 32 vec x 3
__device__ float g_sV1[NODES * 100];   // per-node: sV @ Ws1[0:100] + bs1
__device__ float g_dh [NODES * DIM];   // masked edge-mean of gvp3 output
__device__ float g_hm [NODES * DIM];   // h after first gvp_layernorm
__device__ float g_t4 [NODES * 496];   // gvp4 output (32 vec (96) + 400 scalars)

// =================================================================
// Kernel 0: per-node precompute (k-independent parts of gvp1)
// =================================================================
__global__ __launch_bounds__(256)
void pre_kernel(const float* __restrict__ hV,
                const float* __restrict__ Wh1,
                const float* __restrict__ Ws1,
                const float* __restrict__ bs1)
{
    const int w = threadIdx.x >> 5, lane = threadIdx.x & 31;
    const int node = blockIdx.x * 8 + w;
    if (node >= NODES) return;
    const float* hv = hV + (long)node * DIM;

    // vhV_pre[h=lane][c] = sum_{i<16} vV[i,c] * Wh1[i, h]
    float a0 = 0.f, a1 = 0.f, a2 = 0.f;
#pragma unroll
    for (int i = 0; i < 16; i++) {
        float wt = __ldg(&Wh1[i * 32 + lane]);
        a0 = fmaf(__ldg(&hv[3*i+0]), wt, a0);
        a1 = fmaf(__ldg(&hv[3*i+1]), wt, a1);
        a2 = fmaf(__ldg(&hv[3*i+2]), wt, a2);
    }
    g_vhV[node*96 + lane*3 + 0] = a0;
    g_vhV[node*96 + lane*3 + 1] = a1;
    g_vhV[node*96 + lane*3 + 2] = a2;

    // sV1_pre[j] = sum_{i<100} sV[i]*Ws1[i,j] + bs1[j]
    float s[4];
    int jc[4];
#pragma unroll
    for (int jj = 0; jj < 4; jj++) {
        int j = jj*32 + lane;
        jc[jj] = j < 100 ? j : 99;
        s[jj] = __ldg(&bs1[jc[jj]]);
    }
    for (int i = 0; i < 100; i++) {
        float x = __ldg(&hv[48 + i]);
        const float* wr = Ws1 + i * 100;
#pragma unroll
        for (int jj = 0; jj < 4; jj++) s[jj] = fmaf(x, __ldg(&wr[jc[jj]]), s[jj]);
    }
#pragma unroll
    for (int jj = 0; jj < 4; jj++) {
        int j = jj*32 + lane;
        if (j < 100) g_sV1[node*100 + j] = s[jj];
    }
}

// =================================================================
// Edge kernel helpers
// =================================================================
// batched (3 edges) scalar matmul: out = relu(x @ W + init), W smem [rows][100]
__device__ __forceinline__ void smm3_relu(const float* __restrict__ W, int rows,
    const float* x0, const float* x1, const float* x2,
    const float* init, float* o0, float* o1, float* o2, int lane)
{
    float a0[4], a1[4], a2[4];
    int jc[4];
#pragma unroll
    for (int jj = 0; jj < 4; jj++) {
        int j = jj*32 + lane; jc[jj] = j < 100 ? j : 99;
        float v = init[jc[jj]];
        a0[jj] = v; a1[jj] = v; a2[jj] = v;
    }
#pragma unroll 4
    for (int i = 0; i < rows; i++) {
        float v0 = x0[i], v1 = x1[i], v2 = x2[i];
        const float* wr = W + i * 100;
#pragma unroll
        for (int jj = 0; jj < 4; jj++) {
            float wt = wr[jc[jj]];
            a0[jj] = fmaf(v0, wt, a0[jj]);
            a1[jj] = fmaf(v1, wt, a1[jj]);
            a2[jj] = fmaf(v2, wt, a2[jj]);
        }
    }
#pragma unroll
    for (int jj = 0; jj < 4; jj++) {
        int j = jj*32 + lane;
        if (j < 100) {
            o0[j] = fmaxf(a0[jj], 0.f);
            o1[j] = fmaxf(a1[jj], 0.f);
            o2[j] = fmaxf(a2[jj], 0.f);
        }
    }
}

// hidden transform 16->16: W smem [16][16], in 16 vecs, out 16 vecs + vn
__device__ __forceinline__ void vh16(const float* __restrict__ W,
    const float* in, float* outp, float* vnp, int lane)
{
    if (lane < 16) {
        float a0 = 0.f, a1 = 0.f, a2 = 0.f;
#pragma unroll
        for (int i = 0; i < 16; i++) {
            float wt = W[i*16 + lane];
            a0 = fmaf(in[3*i+0], wt, a0);
            a1 = fmaf(in[3*i+1], wt, a1);
            a2 = fmaf(in[3*i+2], wt, a2);
        }
        outp[3*lane+0] = a0; outp[3*lane+1] = a1; outp[3*lane+2] = a2;
        vnp[lane] = sqrtf(fmaf(a0,a0,fmaf(a1,a1,a2*a2)) + 1e-8f);
    }
}

// gated output transform NIN->16: W smem [NIN][16]
template<int NIN>
__device__ __forceinline__ void vout_gate(const float* __restrict__ W,
    const float* in, float* outp, int lane)
{
    if (lane < 16) {
        float b0 = 0.f, b1 = 0.f, b2 = 0.f;
#pragma unroll
        for (int h = 0; h < NIN; h++) {
            float wt = W[h*16 + lane];
            b0 = fmaf(in[3*h+0], wt, b0);
            b1 = fmaf(in[3*h+1], wt, b1);
            b2 = fmaf(in[3*h+2], wt, b2);
        }
        float nr = sqrtf(fmaf(b0,b0,fmaf(b1,b1,b2*b2)) + 1e-8f);
        float g  = 1.f / (1.f + __expf(-nr));
        outp[3*lane+0] = b0*g; outp[3*lane+1] = b1*g; outp[3*lane+2] = b2*g;
    }
}

// =================================================================
// Kernel 1: edge pipeline (gvp1 -> gvp2 -> gvp3 -> mask -> mean_k)
// =================================================================
// shared layout (floats):
#define O_WH1 0        // Wh1 rows 16..31   [16][32]   512
#define O_WV1 512      // Wv1               [32][16]   512
#define O_WS1 1024     // Ws1 rows 100..231 [132][100] 13200
#define O_WH2 14224    // [16][16] 256
#define O_WV2 14480    // 256
#define O_WS2 14736    // [116][100] 11600
#define O_BS2 26336    // 100
#define O_WH3 26436    // 256
#define O_WV3 26692    // 256
#define O_WS3 26948    // 11600
#define O_BS3 38548    // 100
#define O_NPVH 38648   // 96
#define O_NPS  38744   // 100
#define O_ACC  38844   // 148
#define O_EBUF 38992   // 30 edges * 408
#define EB_STRIDE 408  // vecA@0(48) vecB@48(96) sA@144(132) sB@276(132)
#define EDGE_SMEM ((O_EBUF + 30*EB_STRIDE) * 4)   // 204928 bytes

__global__ __launch_bounds__(320, 1)
void edge_kernel(const float* __restrict__ hM, const int* __restrict__ maskA,
                 const float* __restrict__ Wh1, const float* __restrict__ Wv1,
                 const float* __restrict__ Ws1,
                 const float* __restrict__ Wh2, const float* __restrict__ Wv2,
                 const float* __restrict__ Ws2, const float* __restrict__ bs2,
                 const float* __restrict__ Wh3, const float* __restrict__ Wv3,
                 const float* __restrict__ Ws3, const float* __restrict__ bs3)
{
    extern __shared__ float sm[];
    const int tid = threadIdx.x, w = tid >> 5, lane = tid & 31;

    for (int i = tid; i < 512;   i += 320) sm[O_WH1+i] = __ldg(&Wh1[512 + i]);
    for (int i = tid; i < 512;   i += 320) sm[O_WV1+i] = __ldg(&Wv1[i]);
    for (int i = tid; i < 13200; i += 320) sm[O_WS1+i] = __ldg(&Ws1[10000 + i]);
    for (int i = tid; i < 256;   i += 320) sm[O_WH2+i] = __ldg(&Wh2[i]);
    for (int i = tid; i < 256;   i += 320) sm[O_WV2+i] = __ldg(&Wv2[i]);
    for (int i = tid; i < 11600; i += 320) sm[O_WS2+i] = __ldg(&Ws2[i]);
    for (int i = tid; i < 100;   i += 320) sm[O_BS2+i] = __ldg(&bs2[i]);
    for (int i = tid; i < 256;   i += 320) sm[O_WH3+i] = __ldg(&Wh3[i]);
    for (int i = tid; i < 256;   i += 320) sm[O_WV3+i] = __ldg(&Wv3[i]);
    for (int i = tid; i < 11600; i += 320) sm[O_WS3+i] = __ldg(&Ws3[i]);
    for (int i = tid; i < 100;   i += 320) sm[O_BS3+i] = __ldg(&bs3[i]);
    __syncthreads();

    for (int node = blockIdx.x; node < NODES; node += gridDim.x) {
        for (int i = tid; i < 96;  i += 320) sm[O_NPVH+i] = g_vhV[(long)node*96  + i];
        for (int i = tid; i < 100; i += 320) sm[O_NPS +i] = g_sV1[(long)node*100 + i];
        for (int i = tid; i < 148; i += 320) sm[O_ACC +i] = 0.f;
        __syncthreads();

        float mk[3];
        float* eb[3];
#pragma unroll
        for (int r = 0; r < 3; r++) {
            const int k = w + r * 10;
            eb[r] = sm + O_EBUF + k * EB_STRIDE;
            mk[r] = (float)__ldg(&maskA[(long)node * KK + k]);
            const float* src = hM + ((long)node * KK + k) * DIM;
            for (int t = lane; t < DIM; t += 32) {
                float v = __ldg(&src[t]);
                if (t < 48) eb[r][t] = v;        // vM -> vecA
                else        eb[r][t + 96] = v;   // sM -> sA[0:100] (at 144+)
            }
        }
        __syncwarp();

        // ---- stage 1: vh1 (32 hidden, lane=h) + vn1 ----
#pragma unroll
        for (int r = 0; r < 3; r++) {
            float a0 = sm[O_NPVH + lane*3 + 0];
            float a1 = sm[O_NPVH + lane*3 + 1];
            float a2 = sm[O_NPVH + lane*3 + 2];
            const float* vA = eb[r];
#pragma unroll
            for (int i = 0; i < 16; i++) {
                float wt = sm[O_WH1 + i*32 + lane];
                a0 = fmaf(vA[3*i+0], wt, a0);
                a1 = fmaf(vA[3*i+1], wt, a1);
                a2 = fmaf(vA[3*i+2], wt, a2);
            }
            float* vB = eb[r] + 48;
            vB[lane*3+0] = a0; vB[lane*3+1] = a1; vB[lane*3+2] = a2;
            eb[r][144 + 100 + lane] = sqrtf(fmaf(a0,a0,fmaf(a1,a1,a2*a2)) + 1e-8f);
        }
        __syncwarp();

        // s1: [sM|vn1](132) @ Ws1[100:232] + pre, relu -> sB
        smm3_relu(sm + O_WS1, 132, eb[0]+144, eb[1]+144, eb[2]+144,
                  sm + O_NPS, eb[0]+276, eb[1]+276, eb[2]+276, lane);
        // v1: vecB(32) @ Wv1 gated -> vecA
#pragma unroll
        for (int r = 0; r < 3; r++) vout_gate<32>(sm + O_WV1, eb[r]+48, eb[r], lane);
        __syncwarp();

        // ---- stage 2 ----
#pragma unroll
        for (int r = 0; r < 3; r++) vh16(sm + O_WH2, eb[r], eb[r]+48, eb[r]+276+100, lane);
        __syncwarp();
        smm3_relu(sm + O_WS2, 116, eb[0]+276, eb[1]+276, eb[2]+276,
                  sm + O_BS2, eb[0]+144, eb[1]+144, eb[2]+144, lane);
#pragma unroll
        for (int r = 0; r < 3; r++) vout_gate<16>(sm + O_WV2, eb[r]+48, eb[r], lane);
        __syncwarp();

        // ---- stage 3 (no relu, no gate) ----
#pragma unroll
        for (int r = 0; r < 3; r++) vh16(sm + O_WH3, eb[r], eb[r]+48, eb[r]+144+100, lane);
        __syncwarp();

        // s3: sA[0:116] @ Ws3 + bs3 (no relu), masked-accumulate
        {
            float a0[4], a1[4], a2[4];
            int jc[4];
#pragma unroll
            for (int jj = 0; jj < 4; jj++) {
                int j = jj*32 + lane; jc[jj] = j < 100 ? j : 99;
                float v = sm[O_BS3 + jc[jj]];
                a0[jj] = v; a1[jj] = v; a2[jj] = v;
            }
            const float* x0 = eb[0] + 144;
            const float* x1 = eb[1] + 144;
            const float* x2 = eb[2] + 144;
#pragma unroll 4
            for (int i = 0; i < 116; i++) {
                float v0 = x0[i], v1 = x1[i], v2 = x2[i];
                const float* wr = sm + O_WS3 + i * 100;
#pragma unroll
                for (int jj = 0; jj < 4; jj++) {
                    float wt = wr[jc[jj]];
                    a0[jj] = fmaf(v0, wt, a0[jj]);
                    a1[jj] = fmaf(v1, wt, a1[jj]);
                    a2[jj] = fmaf(v2, wt, a2[jj]);
                }
            }
#pragma unroll
            for (int jj = 0; jj < 4; jj++) {
                int j = jj*32 + lane;
                if (j < 100)
                    atomicAdd(&sm[O_ACC + 48 + j],
                              mk[0]*a0[jj] + mk[1]*a1[jj] + mk[2]*a2[jj]);
            }
        }
        // v3: vecB @ Wv3 (no gate), masked-accumulate
        if (lane < 16) {
            float c0 = 0.f, c1 = 0.f, c2 = 0.f;
#pragma unroll
            for (int r = 0; r < 3; r++) {
                const float* vB = eb[r] + 48;
                float b0 = 0.f, b1 = 0.f, b2 = 0.f;
#pragma unroll
                for (int h = 0; h < 16; h++) {
                    float wt = sm[O_WV3 + h*16 + lane];
                    b0 = fmaf(vB[3*h+0], wt, b0);
                    b1 = fmaf(vB[3*h+1], wt, b1);
                    b2 = fmaf(vB[3*h+2], wt, b2);
                }
                c0 = fmaf(mk[r], b0, c0);
                c1 = fmaf(mk[r], b1, c1);
                c2 = fmaf(mk[r], b2, c2);
            }
            atomicAdd(&sm[O_ACC + lane*3 + 0], c0);
            atomicAdd(&sm[O_ACC + lane*3 + 1], c1);
            atomicAdd(&sm[O_ACC + lane*3 + 2], c2);
        }
        __syncthreads();
        for (int i = tid; i < DIM; i += 320)
            g_dh[(long)node*DIM + i] = sm[O_ACC + i] * (1.f / 30.f);
        __syncthreads();
    }
}

// =================================================================
// Kernel 2: h = gvp_layernorm(h_V + dh)  -> g_hm
// =================================================================
__global__ __launch_bounds__(256)
void ln0_kernel(const float* __restrict__ hV,
                const float* __restrict__ g, const float* __restrict__ b)
{
    const int w = threadIdx.x >> 5, lane = threadIdx.x & 31;
    const int node = blockIdx.x * 8 + w;
    if (node >= NODES) return;
    const float* hv = hV  + (long)node * DIM;
    const float* dh = g_dh + (long)node * DIM;

    float v0 = 0.f, v1 = 0.f, v2 = 0.f, vn2 = 0.f;
    if (lane < 16) {
        v0 = hv[3*lane+0] + dh[3*lane+0];
        v1 = hv[3*lane+1] + dh[3*lane+1];
        v2 = hv[3*lane+2] + dh[3*lane+2];
        vn2 = fmaf(v0,v0,fmaf(v1,v1,v2*v2));
    }
    float t = vn2;
#pragma unroll
    for (int o = 16; o; o >>= 1) t += __shfl_xor_sync(0xffffffffu, t, o);
    float dinv = rsqrtf(t * (1.f/16.f) + 1e-8f);

    float s[4]; float sum = 0.f, sq = 0.f;
    int jc[4];
#pragma unroll
    for (int jj = 0; jj < 4; jj++) {
        int j = jj*32 + lane; jc[jj] = j < 100 ? j : 99;
        s[jj] = (j < 100) ? (hv[48+j] + dh[48+j]) : 0.f;
        sum += s[jj]; sq = fmaf(s[jj], s[jj], sq);
    }
#pragma unroll
    for (int o = 16; o; o >>= 1) {
        sum += __shfl_xor_sync(0xffffffffu, sum, o);
        sq  += __shfl_xor_sync(0xffffffffu, sq,  o);
    }
    float mu  = sum * 0.01f;
    float var = sq * 0.01f - mu*mu;
    float inv = rsqrtf(var + 1e-5f);

    float* o = g_hm + (long)node * DIM;
    if (lane < 16) {
        o[3*lane+0] = v0 * dinv; o[3*lane+1] = v1 * dinv; o[3*lane+2] = v2 * dinv;
    }
#pragma unroll
    for (int jj = 0; jj < 4; jj++) {
        int j = jj*32 + lane;
        if (j < 100) o[48+j] = (s[jj]-mu)*inv*__ldg(&g[j]) + __ldg(&b[j]);
    }
}

// =================================================================
// Kernel 3: gvp4 (16v/100s -> 32v/400s, relu+gate)  -> g_t4
// =================================================================
__global__ __launch_bounds__(256)
void gvp4_kernel(const float* __restrict__ Wh4, const float* __restrict__ Wv4,
                 const float* __restrict__ Ws4, const float* __restrict__ bs4)
{
    const int w = threadIdx.x >> 5, lane = threadIdx.x & 31;
    const int node = blockIdx.x * 8 + w;
    if (node >= NODES) return;
    const float* h = g_hm + (long)node * DIM;

    // vh4: lane = hidden h (32)
    float a0 = 0.f, a1 = 0.f, a2 = 0.f;
#pragma unroll
    for (int i = 0; i < 16; i++) {
        float wt = __ldg(&Wh4[i*32 + lane]);
        a0 = fmaf(__ldg(&h[3*i+0]), wt, a0);
        a1 = fmaf(__ldg(&h[3*i+1]), wt, a1);
        a2 = fmaf(__ldg(&h[3*i+2]), wt, a2);
    }
    float vn = sqrtf(fmaf(a0,a0,fmaf(a1,a1,a2*a2)) + 1e-8f);

    // s: [s(100), vn(32)] @ Ws4(132,400) + bs4, relu. 13 cols/lane.
    float acc[13];
    int jm[13];
#pragma unroll
    for (int jj = 0; jj < 13; jj++) {
        int j = lane + jj*32; jm[jj] = j < 400 ? j : 399;
        acc[jj] = __ldg(&bs4[jm[jj]]);
    }
    for (int i = 0; i < 132; i++) {
        float x = (i < 100) ? __ldg(&h[48+i]) : __shfl_sync(0xffffffffu, vn, i-100);
        const float* wr = Ws4 + i * 400;
#pragma unroll
        for (int jj = 0; jj < 13; jj++) acc[jj] = fmaf(x, __ldg(&wr[jm[jj]]), acc[jj]);
    }
#pragma unroll
    for (int jj = 0; jj < 13; jj++) acc[jj] = fmaxf(acc[jj], 0.f);

    // v: vh4(32) @ Wv4(32,32), gated. lane = out vec (32).
    float b0 = 0.f, b1 = 0.f, b2 = 0.f;
#pragma unroll
    for (int hh = 0; hh < 32; hh++) {
        float wt = __ldg(&Wv4[hh*32 + lane]);
        b0 = fmaf(__shfl_sync(0xffffffffu, a0, hh), wt, b0);
        b1 = fmaf(__shfl_sync(0xffffffffu, a1, hh), wt, b1);
        b2 = fmaf(__shfl_sync(0xffffffffu, a2, hh), wt, b2);
    }
    float nr = sqrtf(fmaf(b0,b0,fmaf(b1,b1,b2*b2)) + 1e-8f);
    float gt = 1.f / (1.f + __expf(-nr));

    float* o = g_t4 + (long)node * 496;
    o[3*lane+0] = b0*gt; o[3*lane+1] = b1*gt; o[3*lane+2] = b2*gt;
#pragma unroll
    for (int jj = 0; jj < 13; jj++) {
        int j = lane + jj*32;
        if (j < 400) o[96+j] = acc[jj];
    }
}

// =================================================================
// Kernel 4: gvp5 (no NL) + residual + ln1 + mask_V -> output
// =================================================================
__global__ __launch_bounds__(256)
void final_kernel(const int* __restrict__ maskV,
                  const float* __restrict__ Wh5, const float* __restrict__ Wv5,
                  const float* __restrict__ Ws5, const float* __restrict__ bs5,
                  const float* __restrict__ g, const float* __restrict__ b,
                  float* __restrict__ out)
{
    const int w = threadIdx.x >> 5, lane = threadIdx.x & 31;
    const int node = blockIdx.x * 8 + w;
    if (node >= NODES) return;
    const float* t = g_t4 + (long)node * 496;

    // vh5: lane = hidden (32); input 32 vecs
    float a0 = 0.f, a1 = 0.f, a2 = 0.f;
#pragma unroll
    for (int i = 0; i < 32; i++) {
        float wt = __ldg(&Wh5[i*32 + lane]);
        a0 = fmaf(__ldg(&t[3*i+0]), wt, a0);
        a1 = fmaf(__ldg(&t[3*i+1]), wt, a1);
        a2 = fmaf(__ldg(&t[3*i+2]), wt, a2);
    }
    float vn = sqrtf(fmaf(a0,a0,fmaf(a1,a1,a2*a2)) + 1e-8f);

    // s5: [s(400), vn(32)] @ Ws5(432,100) + bs5 (no relu). 4 cols/lane.
    float acc[4];
    int jc[4];
#pragma unroll
    for (int jj = 0; jj < 4; jj++) {
        int j = jj*32 + lane; jc[jj] = j < 100 ? j : 99;
        acc[jj] = __ldg(&bs5[jc[jj]]);
    }
    for (int i = 0; i < 432; i++) {
        float x = (i < 400) ? __ldg(&t[96+i]) : __shfl_sync(0xffffffffu, vn, i-400);
        const float* wr = Ws5 + i * 100;
#pragma unroll
        for (int jj = 0; jj < 4; jj++) acc[jj] = fmaf(x, __ldg(&wr[jc[jj]]), acc[jj]);
    }

    // v5: vh5(32) @ Wv5(32,16), no gate. All lanes run shuffles; lane<16 valid.
    float b0 = 0.f, b1 = 0.f, b2 = 0.f;
    const int lc = lane & 15;
#pragma unroll
    for (int hh = 0; hh < 32; hh++) {
        float wt = __ldg(&Wv5[hh*16 + lc]);
        b0 = fmaf(__shfl_sync(0xffffffffu, a0, hh), wt, b0);
        b1 = fmaf(__shfl_sync(0xffffffffu, a1, hh), wt, b1);
        b2 = fmaf(__shfl_sync(0xffffffffu, a2, hh), wt, b2);
    }

    // residual + gvp_layernorm + mask
    const float* hm = g_hm + (long)node * DIM;
    float v0 = 0.f, v1 = 0.f, v2 = 0.f, vn2 = 0.f;
    if (lane < 16) {
        v0 = hm[3*lane+0] + b0;
        v1 = hm[3*lane+1] + b1;
        v2 = hm[3*lane+2] + b2;
        vn2 = fmaf(v0,v0,fmaf(v1,v1,v2*v2));
    }
    float tt = vn2;
#pragma unroll
    for (int o = 16; o; o >>= 1) tt += __shfl_xor_sync(0xffffffffu, tt, o);
    float dinv = rsqrtf(tt * (1.f/16.f) + 1e-8f);

    float s[4]; float sum = 0.f, sq = 0.f;
#pragma unroll
    for (int jj = 0; jj < 4; jj++) {
        int j = jj*32 + lane;
        s[jj] = (j < 100) ? (hm[48+j] + acc[jj]) : 0.f;
        sum += s[jj]; sq = fmaf(s[jj], s[jj], sq);
    }
#pragma unroll
    for (int o = 16; o; o >>= 1) {
        sum += __shfl_xor_sync(0xffffffffu, sum, o);
        sq  += __shfl_xor_sync(0xffffffffu, sq,  o);
    }
    float mu  = sum * 0.01f;
    float var = sq * 0.01f - mu*mu;
    float inv = rsqrtf(var + 1e-5f);

    float m = (float)__ldg(&maskV[node]);
    float* o = out + (long)node * DIM;
    if (lane < 16) {
        o[3*lane+0] = m * v0 * dinv;
        o[3*lane+1] = m * v1 * dinv;
        o[3*lane+2] = m * v2 * dinv;
    }
#pragma unroll
    for (int jj = 0; jj < 4; jj++) {
        int j = jj*32 + lane;
        if (j < 100)
            o[48+j] = m * ((s[jj]-mu)*inv*__ldg(&g[j]) + __ldg(&b[j]));
    }
}

// =================================================================
extern "C" void kernel_launch(void* const* d_in, const int* in_sizes, int n_in,
                              void* d_out, int out_size)
{
    const float* hV    = (const float*)d_in[0];
    const float* hM    = (const float*)d_in[1];
    const int*   maskV = (const int*)  d_in[2];
    const int*   maskA = (const int*)  d_in[3];
    const float* Wh1 = (const float*)d_in[4];
    const float* Wv1 = (const float*)d_in[5];
    const float* Ws1 = (const float*)d_in[6];
    const float* bs1 = (const float*)d_in[7];
    const float* Wh2 = (const float*)d_in[8];
    const float* Wv2 = (const float*)d_in[9];
    const float* Ws2 = (const float*)d_in[10];
    const float* bs2 = (const float*)d_in[11];
    const float* Wh3 = (const float*)d_in[12];
    const float* Wv3 = (const float*)d_in[13];
    const float* Ws3 = (const float*)d_in[14];
    const float* bs3 = (const float*)d_in[15];
    const float* Wh4 = (const float*)d_in[16];
    const float* Wv4 = (const float*)d_in[17];
    const float* Ws4 = (const float*)d_in[18];
    const float* bs4 = (const float*)d_in[19];
    const float* Wh5 = (const float*)d_in[20];
    const float* Wv5 = (const float*)d_in[21];
    const float* Ws5 = (const float*)d_in[22];
    const float* bs5 = (const float*)d_in[23];
    const float* ln0g = (const float*)d_in[24];
    const float* ln0b = (const float*)d_in[25];
    const float* ln1g = (const float*)d_in[26];
    const float* ln1b = (const float*)d_in[27];

    cudaFuncSetAttribute(edge_kernel,
                         cudaFuncAttributeMaxDynamicSharedMemorySize, EDGE_SMEM);

    const int nblk = (NODES + 7) / 8;
    pre_kernel<<<nblk, 256>>>(hV, Wh1, Ws1, bs1);
    edge_kernel<<<148, 320, EDGE_SMEM>>>(hM, maskA, Wh1, Wv1, Ws1,
                                         Wh2, Wv2, Ws2, bs2,
                                         Wh3, Wv3, Ws3, bs3);
    ln0_kernel<<<nblk, 256>>>(hV, ln0g, ln0b);
    gvp4_kernel<<<nblk, 256>>>(Wh4, Wv4, Ws4, bs4);
    final_kernel<<<nblk, 256>>>(maskV, Wh5, Wv5, Ws5, bs5, ln1g, ln1b,
                                (float*)d_out);
}

// round 7
// speedup vs baseline: 1.2071x; 1.2071x over previous
#include <cuda_runtime.h>
#include <cuda_bf16.h>
#include <math.h>

#define BB 2
#define NN 8192
#define KK 30
#define NODES (BB*NN)
#define DIM 148

// ---------------- scratch (static device globals; no allocation) ----------------
__device__ float g_vhV[NODES * 96];    // per-node: Wh1[0:16]^T applied to vV -> 32 vec x 3
__device__ float g_sV1[NODES * 100];   // per-node: sV @ Ws1[0:100] + bs1
__device__ float g_hm [NODES * DIM];   // h after first gvp_layernorm
__device__ float g_t4 [NODES * 496];   // gvp4 output (32 vec (96) + 400 scalars)

__device__ __forceinline__ float f4c(const float4& v, int q) {
    return q == 0 ? v.x : q == 1 ? v.y : q == 2 ? v.z : v.w;
}

// =================================================================
// Kernel 0: per-node precompute (k-independent parts of gvp1)
// persistent CTAs, Ws1[0:100] in smem, 2 nodes per warp
// =================================================================
#define P_W 10000
#define PRE_SMEM ((P_W + 8*200) * 4)

__global__ __launch_bounds__(256, 1)
void pre_kernel(const float* __restrict__ hV,
                const float* __restrict__ Wh1,
                const float* __restrict__ Ws1,
                const float* __restrict__ bs1)
{
    extern __shared__ float sm[];
    const int tid = threadIdx.x, w = tid >> 5, lane = tid & 31;
    for (int i = tid; i < P_W; i += 256) sm[i] = __ldg(&Ws1[i]);
    __syncthreads();
    float* xw = sm + P_W + w * 200;

    for (long base = (long)blockIdx.x * 16; base < NODES; base += (long)gridDim.x * 16) {
        long n0 = base + w * 2, n1 = n0 + 1;
        bool ok0 = n0 < NODES, ok1 = n1 < NODES;
        const float* hv0 = hV + (ok0 ? n0 : 0) * DIM;
        const float* hv1 = hV + (ok1 ? n1 : 0) * DIM;

        // vhV part (lane = hidden 0..31)
#pragma unroll
        for (int e = 0; e < 2; e++) {
            const float* hv = e ? hv1 : hv0;
            float a0 = 0.f, a1 = 0.f, a2 = 0.f;
#pragma unroll
            for (int i = 0; i < 16; i++) {
                float wt = __ldg(&Wh1[i * 32 + lane]);
                a0 = fmaf(hv[3*i+0], wt, a0);
                a1 = fmaf(hv[3*i+1], wt, a1);
                a2 = fmaf(hv[3*i+2], wt, a2);
            }
            bool ok = e ? ok1 : ok0;
            long n = e ? n1 : n0;
            if (ok) {
                g_vhV[n*96 + lane*3 + 0] = a0;
                g_vhV[n*96 + lane*3 + 1] = a1;
                g_vhV[n*96 + lane*3 + 2] = a2;
            }
        }

        // stage scalar inputs
        for (int t = lane; t < 100; t += 32) { xw[t] = hv0[48+t]; xw[100+t] = hv1[48+t]; }
        __syncwarp();

        int jc[4]; float a0[4], a1[4];
#pragma unroll
        for (int jj = 0; jj < 4; jj++) {
            int j = jj*32 + lane; jc[jj] = j < 100 ? j : 99;
            float v = __ldg(&bs1[jc[jj]]);
            a0[jj] = v; a1[jj] = v;
        }
        const float4* x0 = (const float4*)xw;
        const float4* x1 = (const float4*)(xw + 100);
#pragma unroll 2
        for (int i4 = 0; i4 < 25; i4++) {
            float4 va = x0[i4], vb = x1[i4];
            const float* wr = sm + i4 * 400;
#pragma unroll
            for (int q = 0; q < 4; q++) {
                float fa = f4c(va,q), fb = f4c(vb,q);
                const float* wq = wr + q * 100;
#pragma unroll
                for (int jj = 0; jj < 4; jj++) {
                    float wt = wq[jc[jj]];
                    a0[jj] = fmaf(fa, wt, a0[jj]);
                    a1[jj] = fmaf(fb, wt, a1[jj]);
                }
            }
        }
#pragma unroll
        for (int jj = 0; jj < 4; jj++) {
            int j = jj*32 + lane;
            if (j < 100) {
                if (ok0) g_sV1[n0*100 + j] = a0[jj];
                if (ok1) g_sV1[n1*100 + j] = a1[jj];
            }
        }
        __syncwarp();
    }
}

// =================================================================
// Edge kernel helpers
// =================================================================
// batched (5 edges) scalar matmul: o = [relu](x @ W + init)
template<int ROWS, bool RELU>
__device__ __forceinline__ void smm5(const float* __restrict__ W,
    float* eb0, float* eb1, float* eb2, float* eb3, float* eb4,
    int xoff, const float* __restrict__ init, int ooff, int lane)
{
    int jc[4];
    float a0[4], a1[4], a2[4], a3[4], a4[4];
#pragma unroll
    for (int jj = 0; jj < 4; jj++) {
        int j = jj*32 + lane; jc[jj] = j < 100 ? j : 99;
        float v = init[jc[jj]];
        a0[jj]=v; a1[jj]=v; a2[jj]=v; a3[jj]=v; a4[jj]=v;
    }
    const float4* x0 = (const float4*)(eb0 + xoff);
    const float4* x1 = (const float4*)(eb1 + xoff);
    const float4* x2 = (const float4*)(eb2 + xoff);
    const float4* x3 = (const float4*)(eb3 + xoff);
    const float4* x4 = (const float4*)(eb4 + xoff);
#pragma unroll 2
    for (int i4 = 0; i4 < ROWS/4; i4++) {
        float4 v0=x0[i4], v1=x1[i4], v2=x2[i4], v3=x3[i4], v4=x4[i4];
        const float* wr = W + i4 * 400;
#pragma unroll
        for (int q = 0; q < 4; q++) {
            float f0=f4c(v0,q), f1=f4c(v1,q), f2=f4c(v2,q), f3=f4c(v3,q), f4v=f4c(v4,q);
            const float* wq = wr + q * 100;
#pragma unroll
            for (int jj = 0; jj < 4; jj++) {
                float wt = wq[jc[jj]];
                a0[jj]=fmaf(f0,wt,a0[jj]);
                a1[jj]=fmaf(f1,wt,a1[jj]);
                a2[jj]=fmaf(f2,wt,a2[jj]);
                a3[jj]=fmaf(f3,wt,a3[jj]);
                a4[jj]=fmaf(f4v,wt,a4[jj]);
            }
        }
    }
#pragma unroll
    for (int jj = 0; jj < 4; jj++) {
        int j = jj*32 + lane;
        if (j < 100) {
            if (RELU) {
                eb0[ooff+j]=fmaxf(a0[jj],0.f); eb1[ooff+j]=fmaxf(a1[jj],0.f);
                eb2[ooff+j]=fmaxf(a2[jj],0.f); eb3[ooff+j]=fmaxf(a3[jj],0.f);
                eb4[ooff+j]=fmaxf(a4[jj],0.f);
            } else {
                eb0[ooff+j]=a0[jj]; eb1[ooff+j]=a1[jj]; eb2[ooff+j]=a2[jj];
                eb3[ooff+j]=a3[jj]; eb4[ooff+j]=a4[jj];
            }
        }
    }
}

// stage-3 variant: no store, masked accumulate into smem acc (s part at +48)
__device__ __forceinline__ void smm5_acc(const float* __restrict__ W,
    const float* eb0, const float* eb1, const float* eb2, const float* eb3, const float* eb4,
    int xoff, const float* __restrict__ init, const float* mk, float* acc, int lane)
{
    int jc[4];
    float a0[4], a1[4], a2[4], a3[4], a4[4];
#pragma unroll
    for (int jj = 0; jj < 4; jj++) {
        int j = jj*32 + lane; jc[jj] = j < 100 ? j : 99;
        float v = init[jc[jj]];
        a0[jj]=v; a1[jj]=v; a2[jj]=v; a3[jj]=v; a4[jj]=v;
    }
    const float4* x0 = (const float4*)(eb0 + xoff);
    const float4* x1 = (const float4*)(eb1 + xoff);
    const float4* x2 = (const float4*)(eb2 + xoff);
    const float4* x3 = (const float4*)(eb3 + xoff);
    const float4* x4 = (const float4*)(eb4 + xoff);
#pragma unroll 2
    for (int i4 = 0; i4 < 116/4; i4++) {
        float4 v0=x0[i4], v1=x1[i4], v2=x2[i4], v3=x3[i4], v4=x4[i4];
        const float* wr = W + i4 * 400;
#pragma unroll
        for (int q = 0; q < 4; q++) {
            float f0=f4c(v0,q), f1=f4c(v1,q), f2=f4c(v2,q), f3=f4c(v3,q), f4v=f4c(v4,q);
            const float* wq = wr + q * 100;
#pragma unroll
            for (int jj = 0; jj < 4; jj++) {
                float wt = wq[jc[jj]];
                a0[jj]=fmaf(f0,wt,a0[jj]);
                a1[jj]=fmaf(f1,wt,a1[jj]);
                a2[jj]=fmaf(f2,wt,a2[jj]);
                a3[jj]=fmaf(f3,wt,a3[jj]);
                a4[jj]=fmaf(f4v,wt,a4[jj]);
            }
        }
    }
#pragma unroll
    for (int jj = 0; jj < 4; jj++) {
        int j = jj*32 + lane;
        if (j < 100)
            atomicAdd(&acc[48 + j],
                mk[0]*a0[jj] + mk[1]*a1[jj] + mk[2]*a2[jj] + mk[3]*a3[jj] + mk[4]*a4[jj]);
    }
}

// paired (2 edges per warp) hidden transform 16->16 + vn
__device__ __forceinline__ void vh16x2(const float* __restrict__ W,
    const float* i0, const float* i1, float* o0, float* o1,
    float* vn0, float* vn1, int lane, bool dup)
{
    const int l = lane & 15;
    const float* in = (lane < 16) ? i0 : i1;
    float a0=0.f, a1=0.f, a2=0.f;
#pragma unroll
    for (int i = 0; i < 16; i++) {
        float wt = W[i*16 + l];
        a0 = fmaf(in[3*i+0], wt, a0);
        a1 = fmaf(in[3*i+1], wt, a1);
        a2 = fmaf(in[3*i+2], wt, a2);
    }
    if (!dup || lane < 16) {
        float* o  = (lane < 16) ? o0 : o1;
        float* vn = (lane < 16) ? vn0 : vn1;
        o[3*l+0]=a0; o[3*l+1]=a1; o[3*l+2]=a2;
        vn[l] = sqrtf(fmaf(a0,a0,fmaf(a1,a1,a2*a2)) + 1e-8f);
    }
}

// paired gated output transform NIN->16
template<int NIN>
__device__ __forceinline__ void voutx2(const float* __restrict__ W,
    const float* i0, const float* i1, float* o0, float* o1, int lane, bool dup)
{
    const int l = lane & 15;
    const float* in = (lane < 16) ? i0 : i1;
    float b0=0.f, b1=0.f, b2=0.f;
#pragma unroll
    for (int h = 0; h < NIN; h++) {
        float wt = W[h*16 + l];
        b0 = fmaf(in[3*h+0], wt, b0);
        b1 = fmaf(in[3*h+1], wt, b1);
        b2 = fmaf(in[3*h+2], wt, b2);
    }
    float nr = sqrtf(fmaf(b0,b0,fmaf(b1,b1,b2*b2)) + 1e-8f);
    float g  = 1.f / (1.f + __expf(-nr));
    if (!dup || lane < 16) {
        float* o = (lane < 16) ? o0 : o1;
        o[3*l+0]=b0*g; o[3*l+1]=b1*g; o[3*l+2]=b2*g;
    }
}

// paired stage-3 vector out (no gate), masked accumulate
__device__ __forceinline__ void v3x2(const float* __restrict__ W,
    const float* i0, const float* i1, float mk0, float mk1,
    float* accv, int lane, bool dup)
{
    const int l = lane & 15;
    const float* in = (lane < 16) ? i0 : i1;
    float mk = (lane < 16) ? mk0 : mk1;
    float b0=0.f, b1=0.f, b2=0.f;
#pragma unroll
    for (int h = 0; h < 16; h++) {
        float wt = W[h*16 + l];
        b0 = fmaf(in[3*h+0], wt, b0);
        b1 = fmaf(in[3*h+1], wt, b1);
        b2 = fmaf(in[3*h+2], wt, b2);
    }
    if (!dup || lane < 16) {
        atomicAdd(&accv[3*l+0], mk*b0);
        atomicAdd(&accv[3*l+1], mk*b1);
        atomicAdd(&accv[3*l+2], mk*b2);
    }
}

// =================================================================
// Kernel 1: edge pipeline (gvp1 -> gvp2 -> gvp3 -> mask -> mean -> ln0)
// 6 warps x 5 edges
// =================================================================
#define O_WH1 0
#define O_WV1 512
#define O_WS1 1024
#define O_WH2 14224
#define O_WV2 14480
#define O_WS2 14736
#define O_BS2 26336
#define O_WH3 26436
#define O_WV3 26692
#define O_WS3 26948
#define O_BS3 38548
#define O_NPVH 38648
#define O_NPS  38744
#define O_ACC  38844
#define O_EBUF 38992
#define EB_STRIDE 408  // vecA@0(48) vecB@48(96) sA@144(132) sB@276(132)
#define EDGE_SMEM ((O_EBUF + 30*EB_STRIDE) * 4)

__global__ __launch_bounds__(192, 1)
void edge_kernel(const float* __restrict__ hM, const int* __restrict__ maskA,
                 const float* __restrict__ hV,
                 const float* __restrict__ lng, const float* __restrict__ lnb,
                 const float* __restrict__ Wh1, const float* __restrict__ Wv1,
                 const float* __restrict__ Ws1,
                 const float* __restrict__ Wh2, const float* __restrict__ Wv2,
                 const float* __restrict__ Ws2, const float* __restrict__ bs2,
                 const float* __restrict__ Wh3, const float* __restrict__ Wv3,
                 const float* __restrict__ Ws3, const float* __restrict__ bs3)
{
    extern __shared__ float sm[];
    const int tid = threadIdx.x, w = tid >> 5, lane = tid & 31;

    for (int i = tid; i < 512;   i += 192) sm[O_WH1+i] = __ldg(&Wh1[512 + i]);
    for (int i = tid; i < 512;   i += 192) sm[O_WV1+i] = __ldg(&Wv1[i]);
    for (int i = tid; i < 13200; i += 192) sm[O_WS1+i] = __ldg(&Ws1[10000 + i]);
    for (int i = tid; i < 256;   i += 192) sm[O_WH2+i] = __ldg(&Wh2[i]);
    for (int i = tid; i < 256;   i += 192) sm[O_WV2+i] = __ldg(&Wv2[i]);
    for (int i = tid; i < 11600; i += 192) sm[O_WS2+i] = __ldg(&Ws2[i]);
    for (int i = tid; i < 100;   i += 192) sm[O_BS2+i] = __ldg(&bs2[i]);
    for (int i = tid; i < 256;   i += 192) sm[O_WH3+i] = __ldg(&Wh3[i]);
    for (int i = tid; i < 256;   i += 192) sm[O_WV3+i] = __ldg(&Wv3[i]);
    for (int i = tid; i < 11600; i += 192) sm[O_WS3+i] = __ldg(&Ws3[i]);
    for (int i = tid; i < 100;   i += 192) sm[O_BS3+i] = __ldg(&bs3[i]);
    __syncthreads();

    for (int node = blockIdx.x; node < NODES; node += gridDim.x) {
        for (int i = tid; i < 96;  i += 192) sm[O_NPVH+i] = g_vhV[(long)node*96  + i];
        for (int i = tid; i < 100; i += 192) sm[O_NPS +i] = g_sV1[(long)node*100 + i];
        for (int i = tid; i < 148; i += 192) sm[O_ACC +i] = 0.f;
        __syncthreads();

        float mk[5];
        float* eb[5];
#pragma unroll
        for (int r = 0; r < 5; r++) {
            const int k = w * 5 + r;
            eb[r] = sm + O_EBUF + k * EB_STRIDE;
            mk[r] = (float)__ldg(&maskA[(long)node * KK + k]);
            const float* src = hM + ((long)node * KK + k) * DIM;
            for (int t = lane; t < DIM; t += 32) {
                float v = __ldg(&src[t]);
                if (t < 48) eb[r][t] = v;        // vM -> vecA
                else        eb[r][t + 96] = v;   // sM -> sA[0:100]
            }
        }
        __syncwarp();

        // ---- stage 1: vh1 (32 hidden, lane=h) + vn1 ----
#pragma unroll
        for (int r = 0; r < 5; r++) {
            float a0 = sm[O_NPVH + lane*3 + 0];
            float a1 = sm[O_NPVH + lane*3 + 1];
            float a2 = sm[O_NPVH + lane*3 + 2];
            const float* vA = eb[r];
#pragma unroll
            for (int i = 0; i < 16; i++) {
                float wt = sm[O_WH1 + i*32 + lane];
                a0 = fmaf(vA[3*i+0], wt, a0);
                a1 = fmaf(vA[3*i+1], wt, a1);
                a2 = fmaf(vA[3*i+2], wt, a2);
            }
            float* vB = eb[r] + 48;
            vB[lane*3+0] = a0; vB[lane*3+1] = a1; vB[lane*3+2] = a2;
            eb[r][244 + lane] = sqrtf(fmaf(a0,a0,fmaf(a1,a1,a2*a2)) + 1e-8f);
        }
        __syncwarp();

        // s1 + v1
        smm5<132,true>(sm+O_WS1, eb[0],eb[1],eb[2],eb[3],eb[4], 144, sm+O_NPS, 276, lane);
        voutx2<32>(sm+O_WV1, eb[0]+48, eb[1]+48, eb[0], eb[1], lane, false);
        voutx2<32>(sm+O_WV1, eb[2]+48, eb[3]+48, eb[2], eb[3], lane, false);
        voutx2<32>(sm+O_WV1, eb[4]+48, eb[4]+48, eb[4], eb[4], lane, true);
        __syncwarp();

        // ---- stage 2 ----
        vh16x2(sm+O_WH2, eb[0],eb[1], eb[0]+48,eb[1]+48, eb[0]+376,eb[1]+376, lane, false);
        vh16x2(sm+O_WH2, eb[2],eb[3], eb[2]+48,eb[3]+48, eb[2]+376,eb[3]+376, lane, false);
        vh16x2(sm+O_WH2, eb[4],eb[4], eb[4]+48,eb[4]+48, eb[4]+376,eb[4]+376, lane, true);
        __syncwarp();
        smm5<116,true>(sm+O_WS2, eb[0],eb[1],eb[2],eb[3],eb[4], 276, sm+O_BS2, 144, lane);
        voutx2<16>(sm+O_WV2, eb[0]+48, eb[1]+48, eb[0], eb[1], lane, false);
        voutx2<16>(sm+O_WV2, eb[2]+48, eb[3]+48, eb[2], eb[3], lane, false);
        voutx2<16>(sm+O_WV2, eb[4]+48, eb[4]+48, eb[4], eb[4], lane, true);
        __syncwarp();

        // ---- stage 3 (no relu, no gate) ----
        vh16x2(sm+O_WH3, eb[0],eb[1], eb[0]+48,eb[1]+48, eb[0]+244,eb[1]+244, lane, false);
        vh16x2(sm+O_WH3, eb[2],eb[3], eb[2]+48,eb[3]+48, eb[2]+244,eb[3]+244, lane, false);
        vh16x2(sm+O_WH3, eb[4],eb[4], eb[4]+48,eb[4]+48, eb[4]+244,eb[4]+244, lane, true);
        __syncwarp();

        smm5_acc(sm+O_WS3, eb[0],eb[1],eb[2],eb[3],eb[4], 144, sm+O_BS3, mk, sm+O_ACC, lane);
        v3x2(sm+O_WV3, eb[0]+48, eb[1]+48, mk[0], mk[1], sm+O_ACC, lane, false);
        v3x2(sm+O_WV3, eb[2]+48, eb[3]+48, mk[2], mk[3], sm+O_ACC, lane, false);
        v3x2(sm+O_WV3, eb[4]+48, eb[4]+48, mk[4], mk[4], sm+O_ACC, lane, true);
        __syncthreads();

        // ---- fused ln0: h = gvp_layernorm(h_V + acc/30) -> g_hm ----
        if (w == 0) {
            const float* hv = hV + (long)node * DIM;
            const float inv30 = 1.f / 30.f;
            float v0=0.f, v1=0.f, v2=0.f, q=0.f;
            if (lane < 16) {
                v0 = hv[3*lane+0] + sm[O_ACC + 3*lane+0] * inv30;
                v1 = hv[3*lane+1] + sm[O_ACC + 3*lane+1] * inv30;
                v2 = hv[3*lane+2] + sm[O_ACC + 3*lane+2] * inv30;
                q = fmaf(v0,v0,fmaf(v1,v1,v2*v2));
            }
#pragma unroll
            for (int o = 16; o; o >>= 1) q += __shfl_xor_sync(0xffffffffu, q, o);
            float dinv = rsqrtf(q * (1.f/16.f) + 1e-8f);

            float s[4]; float sum = 0.f, sq = 0.f;
#pragma unroll
            for (int jj = 0; jj < 4; jj++) {
                int j = jj*32 + lane;
                s[jj] = (j < 100) ? (hv[48+j] + sm[O_ACC + 48 + j] * inv30) : 0.f;
                sum += s[jj]; sq = fmaf(s[jj], s[jj], sq);
            }
#pragma unroll
            for (int o = 16; o; o >>= 1) {
                sum += __shfl_xor_sync(0xffffffffu, sum, o);
                sq  += __shfl_xor_sync(0xffffffffu, sq,  o);
            }
            float mu  = sum * 0.01f;
            float var = sq * 0.01f - mu*mu;
            float inv = rsqrtf(var + 1e-5f);

            float* o = g_hm + (long)node * DIM;
            if (lane < 16) {
                o[3*lane+0] = v0*dinv; o[3*lane+1] = v1*dinv; o[3*lane+2] = v2*dinv;
            }
#pragma unroll
            for (int jj = 0; jj < 4; jj++) {
                int j = jj*32 + lane;
                if (j < 100) o[48+j] = (s[jj]-mu)*inv*__ldg(&lng[j]) + __ldg(&lnb[j]);
            }
        }
        __syncthreads();
    }
}

// =================================================================
// Kernel 3: gvp4 (16v/100s -> 32v/400s, relu+gate) -> g_t4
// persistent CTAs, Ws4 (211 KB) in smem, 2 nodes/warp
// =================================================================
#define G4_W 52800
#define G4_SMEM ((G4_W + 8*264) * 4)

__global__ __launch_bounds__(256, 1)
void gvp4_kernel(const float* __restrict__ Wh4, const float* __restrict__ Wv4,
                 const float* __restrict__ Ws4, const float* __restrict__ bs4)
{
    extern __shared__ float sm[];
    const int tid = threadIdx.x, w = tid >> 5, lane = tid & 31;
    for (int i = tid; i < G4_W; i += 256) sm[i] = __ldg(&Ws4[i]);
    __syncthreads();
    float* xw = sm + G4_W + w * 264;

    for (long base = (long)blockIdx.x * 16; base < NODES; base += (long)gridDim.x * 16) {
        long n0 = base + w*2, n1 = n0 + 1;
        bool ok0 = n0 < NODES, ok1 = n1 < NODES;
        const float* h0 = g_hm + (ok0 ? n0 : 0) * DIM;
        const float* h1 = g_hm + (ok1 ? n1 : 0) * DIM;

        float A[2][3], vn[2];
#pragma unroll
        for (int e = 0; e < 2; e++) {
            const float* h = e ? h1 : h0;
            float a0=0.f, a1=0.f, a2=0.f;
#pragma unroll
            for (int i = 0; i < 16; i++) {
                float wt = __ldg(&Wh4[i*32 + lane]);
                a0 = fmaf(h[3*i+0], wt, a0);
                a1 = fmaf(h[3*i+1], wt, a1);
                a2 = fmaf(h[3*i+2], wt, a2);
            }
            A[e][0]=a0; A[e][1]=a1; A[e][2]=a2;
            vn[e] = sqrtf(fmaf(a0,a0,fmaf(a1,a1,a2*a2)) + 1e-8f);
        }
        for (int t = lane; t < 100; t += 32) { xw[t] = h0[48+t]; xw[132+t] = h1[48+t]; }
        xw[100+lane] = vn[0]; xw[232+lane] = vn[1];
        __syncwarp();

        float acc0[13], acc1[13];
        int jm[13];
#pragma unroll
        for (int jj = 0; jj < 13; jj++) {
            int j = lane + jj*32; jm[jj] = j < 400 ? j : 399;
            float v = __ldg(&bs4[jm[jj]]);
            acc0[jj] = v; acc1[jj] = v;
        }
        const float4* x0 = (const float4*)xw;
        const float4* x1 = (const float4*)(xw + 132);
        for (int i4 = 0; i4 < 33; i4++) {
            float4 va = x0[i4], vb = x1[i4];
            const float* wr = sm + i4 * 1600;
#pragma unroll
            for (int q = 0; q < 4; q++) {
                float fa = f4c(va,q), fb = f4c(vb,q);
                const float* wq = wr + q * 400;
#pragma unroll
                for (int jj = 0; jj < 13; jj++) {
                    float wt = wq[jm[jj]];
                    acc0[jj] = fmaf(fa, wt, acc0[jj]);
                    acc1[jj] = fmaf(fb, wt, acc1[jj]);
                }
            }
        }
#pragma unroll
        for (int jj = 0; jj < 13; jj++) {
            acc0[jj] = fmaxf(acc0[jj], 0.f);
            acc1[jj] = fmaxf(acc1[jj], 0.f);
        }

        // v part per node (shuffle A), gated
#pragma unroll
        for (int e = 0; e < 2; e++) {
            float b0=0.f, b1=0.f, b2=0.f;
#pragma unroll
            for (int hh = 0; hh < 32; hh++) {
                float wt = __ldg(&Wv4[hh*32 + lane]);
                b0 = fmaf(__shfl_sync(0xffffffffu, A[e][0], hh), wt, b0);
                b1 = fmaf(__shfl_sync(0xffffffffu, A[e][1], hh), wt, b1);
                b2 = fmaf(__shfl_sync(0xffffffffu, A[e][2], hh), wt, b2);
            }
            float nr = sqrtf(fmaf(b0,b0,fmaf(b1,b1,b2*b2)) + 1e-8f);
            float gt = 1.f / (1.f + __expf(-nr));
            bool ok = e ? ok1 : ok0;
            long n = e ? n1 : n0;
            if (ok) {
                float* o = g_t4 + n * 496;
                o[3*lane+0]=b0*gt; o[3*lane+1]=b1*gt; o[3*lane+2]=b2*gt;
                float* acc = e ? acc1 : acc0;
#pragma unroll
                for (int jj = 0; jj < 13; jj++) {
                    int j = lane + jj*32;
                    if (j < 400) o[96+j] = acc[jj];
                }
            }
        }
        __syncwarp();
    }
}

// =================================================================
// Kernel 4: gvp5 (no NL) + residual + ln1 + mask_V -> output
// persistent CTAs, Ws5 (173 KB) in smem, 2 nodes/warp
// =================================================================
#define F_W 43200
#define F_SMEM ((F_W + 8*864) * 4)

__global__ __launch_bounds__(256, 1)
void final_kernel(const int* __restrict__ maskV,
                  const float* __restrict__ Wh5, const float* __restrict__ Wv5,
                  const float* __restrict__ Ws5, const float* __restrict__ bs5,
                  const float* __restrict__ lng, const float* __restrict__ lnb,
                  float* __restrict__ out)
{
    extern __shared__ float sm[];
    const int tid = threadIdx.x, w = tid >> 5, lane = tid & 31;
    for (int i = tid; i < F_W; i += 256) sm[i] = __ldg(&Ws5[i]);
    __syncthreads();
    float* xw = sm + F_W + w * 864;

    for (long base = (long)blockIdx.x * 16; base < NODES; base += (long)gridDim.x * 16) {
        long n0 = base + w*2, n1 = n0 + 1;
        bool ok0 = n0 < NODES, ok1 = n1 < NODES;
        const float* t0 = g_t4 + (ok0 ? n0 : 0) * 496;
        const float* t1 = g_t4 + (ok1 ? n1 : 0) * 496;

        float A[2][3], vn[2];
#pragma unroll
        for (int e = 0; e < 2; e++) {
            const float* t = e ? t1 : t0;
            float a0=0.f, a1=0.f, a2=0.f;
#pragma unroll
            for (int i = 0; i < 32; i++) {
                float wt = __ldg(&Wh5[i*32 + lane]);
                a0 = fmaf(t[3*i+0], wt, a0);
                a1 = fmaf(t[3*i+1], wt, a1);
                a2 = fmaf(t[3*i+2], wt, a2);
            }
            A[e][0]=a0; A[e][1]=a1; A[e][2]=a2;
            vn[e] = sqrtf(fmaf(a0,a0,fmaf(a1,a1,a2*a2)) + 1e-8f);
        }
        for (int t = lane; t < 400; t += 32) { xw[t] = t0[96+t]; xw[432+t] = t1[96+t]; }
        xw[400+lane] = vn[0]; xw[832+lane] = vn[1];
        __syncwarp();

        float acc0[4], acc1[4];
        int jc[4];
#pragma unroll
        for (int jj = 0; jj < 4; jj++) {
            int j = jj*32 + lane; jc[jj] = j < 100 ? j : 99;
            float v = __ldg(&bs5[jc[jj]]);
            acc0[jj] = v; acc1[jj] = v;
        }
        const float4* x0 = (const float4*)xw;
        const float4* x1 = (const float4*)(xw + 432);
#pragma unroll 2
        for (int i4 = 0; i4 < 108; i4++) {
            float4 va = x0[i4], vb = x1[i4];
            const float* wr = sm + i4 * 400;
#pragma unroll
            for (int q = 0; q < 4; q++) {
                float fa = f4c(va,q), fb = f4c(vb,q);
                const float* wq = wr + q * 100;
#pragma unroll
                for (int jj = 0; jj < 4; jj++) {
                    float wt = wq[jc[jj]];
                    acc0[jj] = fmaf(fa, wt, acc0[jj]);
                    acc1[jj] = fmaf(fb, wt, acc1[jj]);
                }
            }
        }

        // v5 (no gate): lane<16 valid, all lanes shuffle
        float Bv[2][3];
        const int lc = lane & 15;
#pragma unroll
        for (int e = 0; e < 2; e++) {
            float b0=0.f, b1=0.f, b2=0.f;
#pragma unroll
            for (int hh = 0; hh < 32; hh++) {
                float wt = __ldg(&Wv5[hh*16 + lc]);
                b0 = fmaf(__shfl_sync(0xffffffffu, A[e][0], hh), wt, b0);
                b1 = fmaf(__shfl_sync(0xffffffffu, A[e][1], hh), wt, b1);
                b2 = fmaf(__shfl_sync(0xffffffffu, A[e][2], hh), wt, b2);
            }
            Bv[e][0]=b0; Bv[e][1]=b1; Bv[e][2]=b2;
        }

        // residual + gvp_layernorm + mask per node
#pragma unroll
        for (int e = 0; e < 2; e++) {
            bool ok = e ? ok1 : ok0;
            long n = e ? n1 : n0;
            const float* hm = g_hm + (ok ? n : 0) * DIM;
            const float* acc = e ? acc1 : acc0;

            float v0=0.f, v1=0.f, v2=0.f, q=0.f;
            if (lane < 16) {
                v0 = hm[3*lane+0] + Bv[e][0];
                v1 = hm[3*lane+1] + Bv[e][1];
                v2 = hm[3*lane+2] + Bv[e][2];
                q = fmaf(v0,v0,fmaf(v1,v1,v2*v2));
            }
#pragma unroll
            for (int o = 16; o; o >>= 1) q += __shfl_xor_sync(0xffffffffu, q, o);
            float dinv = rsqrtf(q * (1.f/16.f) + 1e-8f);

            float s[4]; float sum = 0.f, sq = 0.f;
#pragma unroll
            for (int jj = 0; jj < 4; jj++) {
                int j = jj*32 + lane;
                s[jj] = (j < 100) ? (hm[48+j] + acc[jj]) : 0.f;
                sum += s[jj]; sq = fmaf(s[jj], s[jj], sq);
            }
#pragma unroll
            for (int o = 16; o; o >>= 1) {
                sum += __shfl_xor_sync(0xffffffffu, sum, o);
                sq  += __shfl_xor_sync(0xffffffffu, sq,  o);
            }
            float mu  = sum * 0.01f;
            float var = sq * 0.01f - mu*mu;
            float inv = rsqrtf(var + 1e-5f);

            if (ok) {
                float m = (float)__ldg(&maskV[n]);
                float* o = out + n * DIM;
                if (lane < 16) {
                    o[3*lane+0] = m * v0 * dinv;
                    o[3*lane+1] = m * v1 * dinv;
                    o[3*lane+2] = m * v2 * dinv;
                }
#pragma unroll
                for (int jj = 0; jj < 4; jj++) {
                    int j = jj*32 + lane;
                    if (j < 100)
                        o[48+j] = m * ((s[jj]-mu)*inv*__ldg(&lng[j]) + __ldg(&lnb[j]));
                }
            }
        }
        __syncwarp();
    }
}

// =================================================================
extern "C" void kernel_launch(void* const* d_in, const int* in_sizes, int n_in,
                              void* d_out, int out_size)
{
    const float* hV    = (const float*)d_in[0];
    const float* hM    = (const float*)d_in[1];
    const int*   maskV = (const int*)  d_in[2];
    const int*   maskA = (const int*)  d_in[3];
    const float* Wh1 = (const float*)d_in[4];
    const float* Wv1 = (const float*)d_in[5];
    const float* Ws1 = (const float*)d_in[6];
    const float* bs1 = (const float*)d_in[7];
    const float* Wh2 = (const float*)d_in[8];
    const float* Wv2 = (const float*)d_in[9];
    const float* Ws2 = (const float*)d_in[10];
    const float* bs2 = (const float*)d_in[11];
    const float* Wh3 = (const float*)d_in[12];
    const float* Wv3 = (const float*)d_in[13];
    const float* Ws3 = (const float*)d_in[14];
    const float* bs3 = (const float*)d_in[15];
    const float* Wh4 = (const float*)d_in[16];
    const float* Wv4 = (const float*)d_in[17];
    const float* Ws4 = (const float*)d_in[18];
    const float* bs4 = (const float*)d_in[19];
    const float* Wh5 = (const float*)d_in[20];
    const float* Wv5 = (const float*)d_in[21];
    const float* Ws5 = (const float*)d_in[22];
    const float* bs5 = (const float*)d_in[23];
    const float* ln0g = (const float*)d_in[24];
    const float* ln0b = (const float*)d_in[25];
    const float* ln1g = (const float*)d_in[26];
    const float* ln1b = (const float*)d_in[27];

    static int attr_done = 0;
    if (!attr_done) {
        cudaFuncSetAttribute(pre_kernel,
                             cudaFuncAttributeMaxDynamicSharedMemorySize, PRE_SMEM);
        cudaFuncSetAttribute(edge_kernel,
                             cudaFuncAttributeMaxDynamicSharedMemorySize, EDGE_SMEM);
        cudaFuncSetAttribute(gvp4_kernel,
                             cudaFuncAttributeMaxDynamicSharedMemorySize, G4_SMEM);
        cudaFuncSetAttribute(final_kernel,
                             cudaFuncAttributeMaxDynamicSharedMemorySize, F_SMEM);
        attr_done = 1;
    }

    pre_kernel <<<148, 256, PRE_SMEM >>>(hV, Wh1, Ws1, bs1);
    edge_kernel<<<148, 192, EDGE_SMEM>>>(hM, maskA, hV, ln0g, ln0b,
                                         Wh1, Wv1, Ws1,
                                         Wh2, Wv2, Ws2, bs2,
                                         Wh3, Wv3, Ws3, bs3);
    gvp4_kernel<<<148, 256, G4_SMEM>>>(Wh4, Wv4, Ws4, bs4);
    final_kernel<<<148, 256, F_SMEM>>>(maskV, Wh5, Wv5, Ws5, bs5, ln1g, ln1b,
                                       (float*)d_out);
}

// round 8
// speedup vs baseline: 1.2899x; 1.0686x over previous
#include <cuda_runtime.h>
#include <cuda_bf16.h>
#include <math.h>

#define BB 2
#define NN 8192
#define KK 30
#define NODES (BB*NN)
#define DIM 148

// ---------------- scratch (static device globals; no allocation) ----------------
__device__ float g_vhV[NODES * 96];    // per-node: Wh1[0:16]^T applied to vV -> 32 vec x 3
__device__ float g_sV1[NODES * 100];   // per-node: sV @ Ws1[0:100] + bs1
__device__ float g_hm [NODES * DIM];   // h after first gvp_layernorm
__device__ float g_t4 [NODES * 496];   // gvp4 output (32 vec (96) + 400 scalars)

__device__ __forceinline__ float f4c(const float4& v, int q) {
    return q == 0 ? v.x : q == 1 ? v.y : q == 2 ? v.z : v.w;
}

__device__ __forceinline__ unsigned tf32u(float f) {
    unsigned u;
    asm("cvt.rna.tf32.f32 %0, %1;" : "=r"(u) : "f"(f));
    return u;
}
__device__ __forceinline__ float tf32f(float f) {
    return __uint_as_float(tf32u(f));
}

__device__ __forceinline__ void mma8(float c[4], const unsigned a[4], unsigned b0, unsigned b1) {
    asm volatile(
        "mma.sync.aligned.m16n8k8.row.col.f32.tf32.tf32.f32 "
        "{%0,%1,%2,%3}, {%4,%5,%6,%7}, {%8,%9}, {%0,%1,%2,%3};"
        : "+f"(c[0]), "+f"(c[1]), "+f"(c[2]), "+f"(c[3])
        : "r"(a[0]), "r"(a[1]), "r"(a[2]), "r"(a[3]), "r"(b0), "r"(b1));
}

// =================================================================
// Kernel 0: per-node precompute (k-independent parts of gvp1)
// =================================================================
#define P_W 10000
#define PRE_SMEM ((P_W + 8*200) * 4)

__global__ __launch_bounds__(256, 1)
void pre_kernel(const float* __restrict__ hV,
                const float* __restrict__ Wh1,
                const float* __restrict__ Ws1,
                const float* __restrict__ bs1)
{
    extern __shared__ float sm[];
    const int tid = threadIdx.x, w = tid >> 5, lane = tid & 31;
    for (int i = tid; i < P_W; i += 256) sm[i] = __ldg(&Ws1[i]);
    __syncthreads();
    float* xw = sm + P_W + w * 200;

    for (long base = (long)blockIdx.x * 16; base < NODES; base += (long)gridDim.x * 16) {
        long n0 = base + w * 2, n1 = n0 + 1;
        bool ok0 = n0 < NODES, ok1 = n1 < NODES;
        const float* hv0 = hV + (ok0 ? n0 : 0) * DIM;
        const float* hv1 = hV + (ok1 ? n1 : 0) * DIM;

#pragma unroll
        for (int e = 0; e < 2; e++) {
            const float* hv = e ? hv1 : hv0;
            float a0 = 0.f, a1 = 0.f, a2 = 0.f;
#pragma unroll
            for (int i = 0; i < 16; i++) {
                float wt = __ldg(&Wh1[i * 32 + lane]);
                a0 = fmaf(hv[3*i+0], wt, a0);
                a1 = fmaf(hv[3*i+1], wt, a1);
                a2 = fmaf(hv[3*i+2], wt, a2);
            }
            bool ok = e ? ok1 : ok0;
            long n = e ? n1 : n0;
            if (ok) {
                g_vhV[n*96 + lane*3 + 0] = a0;
                g_vhV[n*96 + lane*3 + 1] = a1;
                g_vhV[n*96 + lane*3 + 2] = a2;
            }
        }

        for (int t = lane; t < 100; t += 32) { xw[t] = hv0[48+t]; xw[100+t] = hv1[48+t]; }
        __syncwarp();

        int jc[4]; float a0[4], a1[4];
#pragma unroll
        for (int jj = 0; jj < 4; jj++) {
            int j = jj*32 + lane; jc[jj] = j < 100 ? j : 99;
            float v = __ldg(&bs1[jc[jj]]);
            a0[jj] = v; a1[jj] = v;
        }
        const float4* x0 = (const float4*)xw;
        const float4* x1 = (const float4*)(xw + 100);
#pragma unroll 2
        for (int i4 = 0; i4 < 25; i4++) {
            float4 va = x0[i4], vb = x1[i4];
            const float* wr = sm + i4 * 400;
#pragma unroll
            for (int q = 0; q < 4; q++) {
                float fa = f4c(va,q), fb = f4c(vb,q);
                const float* wq = wr + q * 100;
#pragma unroll
                for (int jj = 0; jj < 4; jj++) {
                    float wt = wq[jc[jj]];
                    a0[jj] = fmaf(fa, wt, a0[jj]);
                    a1[jj] = fmaf(fb, wt, a1[jj]);
                }
            }
        }
#pragma unroll
        for (int jj = 0; jj < 4; jj++) {
            int j = jj*32 + lane;
            if (j < 100) {
                if (ok0) g_sV1[n0*100 + j] = a0[jj];
                if (ok1) g_sV1[n1*100 + j] = a1[jj];
            }
        }
        __syncwarp();
    }
}

// =================================================================
// Edge kernel: tf32 tensor-core s-matmuls + fp32 vector path
// 512 threads = 16 warps; 1 node per CTA iteration.
// =================================================================
// shared layout (float indices):
#define O_W1   0        // [136][104] tf32 (Ws1 rows 100..231, zero-padded)
#define O_W2   14144    // [120][104] tf32 (Ws2)
#define O_W3   26624    // [120][104] tf32 (Ws3)
#define O_WH1  39104    // Wh1 rows 16..31 [16][32]
#define O_WV1  39616    // [32][16]
#define O_WH2  40128    // [16][16]
#define O_WV2  40384
#define O_WH3  40640
#define O_WV3  40896
#define O_BS2  41152    // 100
#define O_BS3  41252    // 100
#define O_PVH  41352    // 96
#define O_PRS  41448    // 100 (fp32, exact)
#define O_ACC  41548    // 148
#define O_MK   41696    // 32
#define O_VEC  41728    // 30 edges * 144 (vecA 48 | vecB 96)
#define O_X1   46048    // [32][140]  (X3 aliases this, stride 124)
#define O_X2   50528    // [32][124]
#define SM_FLOATS 54496
#define EDGE_SMEM (SM_FLOATS * 4)   // 217,984 B

#define XS1 140
#define XS2 124
#define WS  104

// MMA over KT k-tiles: warp w (0..6) handles n-tiles {2w, 2w+1(<13)}, m-tiles {0,1}
__device__ __forceinline__ void mma_stage(const unsigned* __restrict__ X, int XS,
                                          const unsigned* __restrict__ Wm, int KT,
                                          int gid, int tig, int w, float C[2][2][4])
{
    const bool nt1ok = (2*w+1) < 13;
    const int col0 = 8*(2*w) + gid;
    const int col1 = nt1ok ? (8*(2*w+1) + gid) : col0;
#pragma unroll 2
    for (int kt = 0; kt < KT; kt++) {
        const int k0 = kt * 8;
        unsigned a[2][4];
#pragma unroll
        for (int mt = 0; mt < 2; mt++) {
            const unsigned* xr = X + (16*mt + gid)*XS + k0 + tig;
            a[mt][0] = xr[0];
            a[mt][1] = xr[8*XS];
            a[mt][2] = xr[4];
            a[mt][3] = xr[8*XS + 4];
        }
        const unsigned* wr = Wm + (k0 + tig)*WS;
        unsigned b00 = wr[col0], b01 = wr[4*WS + col0];
        unsigned b10 = wr[col1], b11 = wr[4*WS + col1];
#pragma unroll
        for (int mt = 0; mt < 2; mt++) {
            mma8(C[mt][0], a[mt], b00, b01);
            if (nt1ok) mma8(C[mt][1], a[mt], b10, b11);
        }
    }
}

// store C -> Xo (stride XSo) with relu, addend, tf32 round
__device__ __forceinline__ void store_stage(float* __restrict__ Xo, int XSo,
                                            const float* __restrict__ addend,
                                            const float C[2][2][4],
                                            int gid, int tig, int w)
{
#pragma unroll
    for (int mt = 0; mt < 2; mt++)
#pragma unroll
    for (int nti = 0; nti < 2; nti++) {
        int nt = 2*w + nti;
        if (nt >= 13) continue;
#pragma unroll
        for (int r = 0; r < 4; r++) {
            int edge = 16*mt + gid + ((r >> 1) << 3);
            int n = 8*nt + 2*tig + (r & 1);
            if (edge < 30 && n < 100)
                Xo[edge*XSo + n] = tf32f(fmaxf(C[mt][nti][r] + addend[n], 0.f));
        }
    }
}

__global__ __launch_bounds__(512, 1)
void edge_kernel(const float* __restrict__ hM, const int* __restrict__ maskA,
                 const float* __restrict__ hV,
                 const float* __restrict__ lng, const float* __restrict__ lnb,
                 const float* __restrict__ Wh1, const float* __restrict__ Wv1,
                 const float* __restrict__ Ws1,
                 const float* __restrict__ Wh2, const float* __restrict__ Wv2,
                 const float* __restrict__ Ws2, const float* __restrict__ bs2,
                 const float* __restrict__ Wh3, const float* __restrict__ Wv3,
                 const float* __restrict__ Ws3, const float* __restrict__ bs3)
{
    extern __shared__ float sm[];
    unsigned* usm = (unsigned*)sm;
    const int tid = threadIdx.x, w = tid >> 5, lane = tid & 31;
    const int gid = lane >> 2, tig = lane & 3;

    // ---- one-time fills ----
    for (int i = tid; i < 136*WS; i += 512) {
        int k = i / WS, n = i - k*WS;
        sm[O_W1+i] = (k < 132 && n < 100) ? tf32f(__ldg(&Ws1[(100+k)*100 + n])) : 0.f;
    }
    for (int i = tid; i < 120*WS; i += 512) {
        int k = i / WS, n = i - k*WS;
        sm[O_W2+i] = (k < 116 && n < 100) ? tf32f(__ldg(&Ws2[k*100 + n])) : 0.f;
        sm[O_W3+i] = (k < 116 && n < 100) ? tf32f(__ldg(&Ws3[k*100 + n])) : 0.f;
    }
    for (int i = tid; i < 512; i += 512) { sm[O_WH1+i] = __ldg(&Wh1[512+i]); sm[O_WV1+i] = __ldg(&Wv1[i]); }
    if (tid < 256) {
        sm[O_WH2+tid] = __ldg(&Wh2[tid]);  sm[O_WV2+tid] = __ldg(&Wv2[tid]);
        sm[O_WH3+tid] = __ldg(&Wh3[tid]);  sm[O_WV3+tid] = __ldg(&Wv3[tid]);
    }
    if (tid < 100) { sm[O_BS2+tid] = __ldg(&bs2[tid]); sm[O_BS3+tid] = __ldg(&bs3[tid]); }
    // zero X2 fully; zero X1 rows 30,31 (never rewritten)
    for (int i = tid; i < 32*XS2; i += 512) sm[O_X2+i] = 0.f;
    for (int i = tid; i < 2*XS1;  i += 512) sm[O_X1 + 30*XS1 + i] = 0.f;
    __syncthreads();

    for (int node = blockIdx.x; node < NODES; node += gridDim.x) {
        // ---- P0: stage node + edges ----
        for (int i = tid; i < 148; i += 512) sm[O_ACC+i] = 0.f;
        for (int i = tid; i < 96;  i += 512) sm[O_PVH+i] = g_vhV[(long)node*96  + i];
        for (int i = tid; i < 100; i += 512) sm[O_PRS+i] = g_sV1[(long)node*100 + i];
        if (tid < 30) sm[O_MK+tid] = (float)__ldg(&maskA[(long)node*KK + tid]);
        {
            const float* src = hM + (long)node * KK * DIM;
            for (int idx = tid; idx < KK*DIM; idx += 512) {
                int e = idx / DIM, t = idx - e*DIM;
                float v = __ldg(&src[idx]);
                if (t < 48) sm[O_VEC + e*144 + t] = v;                 // vM -> vecA
                else        sm[O_X1  + e*XS1 + (t-48)] = tf32f(v);     // sM -> X1 cols 0..99
            }
            for (int i = tid; i < 30*8; i += 512) {                    // X1 pad cols 132..139
                int e = i >> 3;
                sm[O_X1 + e*XS1 + 132 + (i & 7)] = 0.f;
            }
        }
        __syncthreads();

        // ---- P1: vh1 (full warp per edge, 2 edges per warp) -> vecB(32 vecs) + vn1 -> X1 cols 100..131
        if (w < 15) {
#pragma unroll
            for (int r = 0; r < 2; r++) {
                int e = 2*w + r;
                const float* vA = sm + O_VEC + e*144;
                float a0 = sm[O_PVH + lane*3 + 0];
                float a1 = sm[O_PVH + lane*3 + 1];
                float a2 = sm[O_PVH + lane*3 + 2];
#pragma unroll
                for (int i = 0; i < 16; i++) {
                    float wt = sm[O_WH1 + i*32 + lane];
                    a0 = fmaf(vA[3*i+0], wt, a0);
                    a1 = fmaf(vA[3*i+1], wt, a1);
                    a2 = fmaf(vA[3*i+2], wt, a2);
                }
                float* vB = sm + O_VEC + e*144 + 48;
                vB[3*lane+0] = a0; vB[3*lane+1] = a1; vB[3*lane+2] = a2;
                sm[O_X1 + e*XS1 + 100 + lane] =
                    tf32f(sqrtf(fmaf(a0,a0,fmaf(a1,a1,a2*a2)) + 1e-8f));
            }
        }
        __syncthreads();

        // ---- P2: stage-1 MMA: X1[32x132+] @ W1 -> X2 (relu, + exact fp32 node addend)
        if (w < 7) {
            float C[2][2][4] = {};
            mma_stage(usm + O_X1, XS1, usm + O_W1, 17, gid, tig, w, C);
            store_stage(sm + O_X2, XS2, sm + O_PRS, C, gid, tig, w);
        }
        __syncthreads();

        // ---- P3: v1 gated (half-warp per edge), vh2 -> vn2 in X2 cols 100..115
        if (w < 15) {
            const int l = lane & 15;
            const int e = 2*w + (lane >> 4);
            float* vA = sm + O_VEC + e*144;
            float* vB = vA + 48;
            {   // v1: 32 -> 16, gated
                float b0=0.f, b1=0.f, b2=0.f;
#pragma unroll
                for (int h = 0; h < 32; h++) {
                    float wt = sm[O_WV1 + h*16 + l];
                    b0 = fmaf(vB[3*h+0], wt, b0);
                    b1 = fmaf(vB[3*h+1], wt, b1);
                    b2 = fmaf(vB[3*h+2], wt, b2);
                }
                float nr = sqrtf(fmaf(b0,b0,fmaf(b1,b1,b2*b2)) + 1e-8f);
                float g = 1.f / (1.f + __expf(-nr));
                vA[3*l+0]=b0*g; vA[3*l+1]=b1*g; vA[3*l+2]=b2*g;
            }
            __syncwarp();
            {   // vh2: 16 -> 16 + vn2
                float a0=0.f, a1=0.f, a2=0.f;
#pragma unroll
                for (int i = 0; i < 16; i++) {
                    float wt = sm[O_WH2 + i*16 + l];
                    a0 = fmaf(vA[3*i+0], wt, a0);
                    a1 = fmaf(vA[3*i+1], wt, a1);
                    a2 = fmaf(vA[3*i+2], wt, a2);
                }
                vB[3*l+0]=a0; vB[3*l+1]=a1; vB[3*l+2]=a2;
                sm[O_X2 + e*XS2 + 100 + l] =
                    tf32f(sqrtf(fmaf(a0,a0,fmaf(a1,a1,a2*a2)) + 1e-8f));
            }
        } else if (w == 15) {
            // zero X3 pads (X3 aliases X1, stride 124): cols 116..123 rows 0..29, rows 30,31 full
            for (int i = lane; i < 30*8; i += 32) {
                int e = i >> 3;
                sm[O_X1 + e*XS2 + 116 + (i & 7)] = 0.f;
            }
            for (int i = lane; i < 2*XS2; i += 32) sm[O_X1 + 30*XS2 + i] = 0.f;
        }
        __syncthreads();

        // ---- P4: stage-2 MMA: X2 @ W2 -> X3 (relu + bs2)
        if (w < 7) {
            float C[2][2][4] = {};
            mma_stage(usm + O_X2, XS2, usm + O_W2, 15, gid, tig, w, C);
            store_stage(sm + O_X1, XS2, sm + O_BS2, C, gid, tig, w);  // X3 = X1 space, stride 124
        }
        __syncthreads();

        // ---- P5: v2 gated, vh3 -> vn3 in X3, v3 masked vector accumulate
        if (w < 15) {
            const int l = lane & 15;
            const int e = 2*w + (lane >> 4);
            float* vA = sm + O_VEC + e*144;
            float* vB = vA + 48;
            {   // v2: 16 -> 16, gated
                float b0=0.f, b1=0.f, b2=0.f;
#pragma unroll
                for (int h = 0; h < 16; h++) {
                    float wt = sm[O_WV2 + h*16 + l];
                    b0 = fmaf(vB[3*h+0], wt, b0);
                    b1 = fmaf(vB[3*h+1], wt, b1);
                    b2 = fmaf(vB[3*h+2], wt, b2);
                }
                float nr = sqrtf(fmaf(b0,b0,fmaf(b1,b1,b2*b2)) + 1e-8f);
                float g = 1.f / (1.f + __expf(-nr));
                vA[3*l+0]=b0*g; vA[3*l+1]=b1*g; vA[3*l+2]=b2*g;
            }
            __syncwarp();
            {   // vh3: 16 -> 16 + vn3
                float a0=0.f, a1=0.f, a2=0.f;
#pragma unroll
                for (int i = 0; i < 16; i++) {
                    float wt = sm[O_WH3 + i*16 + l];
                    a0 = fmaf(vA[3*i+0], wt, a0);
                    a1 = fmaf(vA[3*i+1], wt, a1);
                    a2 = fmaf(vA[3*i+2], wt, a2);
                }
                vB[3*l+0]=a0; vB[3*l+1]=a1; vB[3*l+2]=a2;
                sm[O_X1 + e*XS2 + 100 + l] =
                    tf32f(sqrtf(fmaf(a0,a0,fmaf(a1,a1,a2*a2)) + 1e-8f));
            }
            __syncwarp();
            {   // v3: 16 -> 16, no gate, masked accumulate
                float mk = sm[O_MK + e];
                float b0=0.f, b1=0.f, b2=0.f;
#pragma unroll
                for (int h = 0; h < 16; h++) {
                    float wt = sm[O_WV3 + h*16 + l];
                    b0 = fmaf(vB[3*h+0], wt, b0);
                    b1 = fmaf(vB[3*h+1], wt, b1);
                    b2 = fmaf(vB[3*h+2], wt, b2);
                }
                atomicAdd(&sm[O_ACC + 3*l+0], mk*b0);
                atomicAdd(&sm[O_ACC + 3*l+1], mk*b1);
                atomicAdd(&sm[O_ACC + 3*l+2], mk*b2);
            }
        }
        __syncthreads();

        // ---- P6: stage-3 MMA: X3 @ W3, masked scalar accumulate (bias handled in P7)
        if (w < 7) {
            float C[2][2][4] = {};
            mma_stage(usm + O_X1, XS2, usm + O_W3, 15, gid, tig, w, C);
#pragma unroll
            for (int mt = 0; mt < 2; mt++)
#pragma unroll
            for (int nti = 0; nti < 2; nti++) {
                int nt = 2*w + nti;
                if (nt >= 13) continue;
#pragma unroll
                for (int r = 0; r < 4; r++) {
                    int edge = 16*mt + gid + ((r >> 1) << 3);
                    int n = 8*nt + 2*tig + (r & 1);
                    if (edge < 30 && n < 100)
                        atomicAdd(&sm[O_ACC + 48 + n], sm[O_MK + edge] * C[mt][nti][r]);
                }
            }
        }
        __syncthreads();

        // ---- P7: ln0 on (h_V + mean) -> g_hm
        if (w == 0) {
            float smk = (lane < 30) ? sm[O_MK + lane] : 0.f;
#pragma unroll
            for (int o = 16; o; o >>= 1) smk += __shfl_xor_sync(0xffffffffu, smk, o);

            const float* hv = hV + (long)node * DIM;
            const float inv30 = 1.f / 30.f;
            float v0=0.f, v1=0.f, v2=0.f, q=0.f;
            if (lane < 16) {
                v0 = hv[3*lane+0] + sm[O_ACC + 3*lane+0] * inv30;
                v1 = hv[3*lane+1] + sm[O_ACC + 3*lane+1] * inv30;
                v2 = hv[3*lane+2] + sm[O_ACC + 3*lane+2] * inv30;
                q = fmaf(v0,v0,fmaf(v1,v1,v2*v2));
            }
#pragma unroll
            for (int o = 16; o; o >>= 1) q += __shfl_xor_sync(0xffffffffu, q, o);
            float dinv = rsqrtf(q * (1.f/16.f) + 1e-8f);

            float s[4]; float sum = 0.f, sq = 0.f;
#pragma unroll
            for (int jj = 0; jj < 4; jj++) {
                int j = jj*32 + lane;
                s[jj] = (j < 100)
                    ? (hv[48+j] + (sm[O_ACC + 48 + j] + sm[O_BS3+j]*smk) * inv30) : 0.f;
                sum += s[jj]; sq = fmaf(s[jj], s[jj], sq);
            }
#pragma unroll
            for (int o = 16; o; o >>= 1) {
                sum += __shfl_xor_sync(0xffffffffu, sum, o);
                sq  += __shfl_xor_sync(0xffffffffu, sq,  o);
            }
            float mu  = sum * 0.01f;
            float var = sq * 0.01f - mu*mu;
            float inv = rsqrtf(var + 1e-5f);

            float* o = g_hm + (long)node * DIM;
            if (lane < 16) {
                o[3*lane+0] = v0*dinv; o[3*lane+1] = v1*dinv; o[3*lane+2] = v2*dinv;
            }
#pragma unroll
            for (int jj = 0; jj < 4; jj++) {
                int j = jj*32 + lane;
                if (j < 100) o[48+j] = (s[jj]-mu)*inv*__ldg(&lng[j]) + __ldg(&lnb[j]);
            }
        }
        __syncthreads();
    }
}

// =================================================================
// Kernel 3: gvp4 (16v/100s -> 32v/400s, relu+gate) -> g_t4
// =================================================================
#define G4_W 52800
#define G4_SMEM ((G4_W + 8*264) * 4)

__global__ __launch_bounds__(256, 1)
void gvp4_kernel(const float* __restrict__ Wh4, const float* __restrict__ Wv4,
                 const float* __restrict__ Ws4, const float* __restrict__ bs4)
{
    extern __shared__ float sm[];
    const int tid = threadIdx.x, w = tid >> 5, lane = tid & 31;
    for (int i = tid; i < G4_W; i += 256) sm[i] = __ldg(&Ws4[i]);
    __syncthreads();
    float* xw = sm + G4_W + w * 264;

    for (long base = (long)blockIdx.x * 16; base < NODES; base += (long)gridDim.x * 16) {
        long n0 = base + w*2, n1 = n0 + 1;
        bool ok0 = n0 < NODES, ok1 = n1 < NODES;
        const float* h0 = g_hm + (ok0 ? n0 : 0) * DIM;
        const float* h1 = g_hm + (ok1 ? n1 : 0) * DIM;

        float A[2][3], vn[2];
#pragma unroll
        for (int e = 0; e < 2; e++) {
            const float* h = e ? h1 : h0;
            float a0=0.f, a1=0.f, a2=0.f;
#pragma unroll
            for (int i = 0; i < 16; i++) {
                float wt = __ldg(&Wh4[i*32 + lane]);
                a0 = fmaf(h[3*i+0], wt, a0);
                a1 = fmaf(h[3*i+1], wt, a1);
                a2 = fmaf(h[3*i+2], wt, a2);
            }
            A[e][0]=a0; A[e][1]=a1; A[e][2]=a2;
            vn[e] = sqrtf(fmaf(a0,a0,fmaf(a1,a1,a2*a2)) + 1e-8f);
        }
        for (int t = lane; t < 100; t += 32) { xw[t] = h0[48+t]; xw[132+t] = h1[48+t]; }
        xw[100+lane] = vn[0]; xw[232+lane] = vn[1];
        __syncwarp();

        float acc0[13], acc1[13];
        int jm[13];
#pragma unroll
        for (int jj = 0; jj < 13; jj++) {
            int j = lane + jj*32; jm[jj] = j < 400 ? j : 399;
            float v = __ldg(&bs4[jm[jj]]);
            acc0[jj] = v; acc1[jj] = v;
        }
        const float4* x0 = (const float4*)xw;
        const float4* x1 = (const float4*)(xw + 132);
        for (int i4 = 0; i4 < 33; i4++) {
            float4 va = x0[i4], vb = x1[i4];
            const float* wr = sm + i4 * 1600;
#pragma unroll
            for (int q = 0; q < 4; q++) {
                float fa = f4c(va,q), fb = f4c(vb,q);
                const float* wq = wr + q * 400;
#pragma unroll
                for (int jj = 0; jj < 13; jj++) {
                    float wt = wq[jm[jj]];
                    acc0[jj] = fmaf(fa, wt, acc0[jj]);
                    acc1[jj] = fmaf(fb, wt, acc1[jj]);
                }
            }
        }
#pragma unroll
        for (int jj = 0; jj < 13; jj++) {
            acc0[jj] = fmaxf(acc0[jj], 0.f);
            acc1[jj] = fmaxf(acc1[jj], 0.f);
        }

#pragma unroll
        for (int e = 0; e < 2; e++) {
            float b0=0.f, b1=0.f, b2=0.f;
#pragma unroll
            for (int hh = 0; hh < 32; hh++) {
                float wt = __ldg(&Wv4[hh*32 + lane]);
                b0 = fmaf(__shfl_sync(0xffffffffu, A[e][0], hh), wt, b0);
                b1 = fmaf(__shfl_sync(0xffffffffu, A[e][1], hh), wt, b1);
                b2 = fmaf(__shfl_sync(0xffffffffu, A[e][2], hh), wt, b2);
            }
            float nr = sqrtf(fmaf(b0,b0,fmaf(b1,b1,b2*b2)) + 1e-8f);
            float gt = 1.f / (1.f + __expf(-nr));
            bool ok = e ? ok1 : ok0;
            long n = e ? n1 : n0;
            if (ok) {
                float* o = g_t4 + n * 496;
                o[3*lane+0]=b0*gt; o[3*lane+1]=b1*gt; o[3*lane+2]=b2*gt;
                float* acc = e ? acc1 : acc0;
#pragma unroll
                for (int jj = 0; jj < 13; jj++) {
                    int j = lane + jj*32;
                    if (j < 400) o[96+j] = acc[jj];
                }
            }
        }
        __syncwarp();
    }
}

// =================================================================
// Kernel 4: gvp5 (no NL) + residual + ln1 + mask_V -> output
// =================================================================
#define F_W 43200
#define F_SMEM ((F_W + 8*864) * 4)

__global__ __launch_bounds__(256, 1)
void final_kernel(const int* __restrict__ maskV,
                  const float* __restrict__ Wh5, const float* __restrict__ Wv5,
                  const float* __restrict__ Ws5, const float* __restrict__ bs5,
                  const float* __restrict__ lng, const float* __restrict__ lnb,
                  float* __restrict__ out)
{
    extern __shared__ float sm[];
    const int tid = threadIdx.x, w = tid >> 5, lane = tid & 31;
    for (int i = tid; i < F_W; i += 256) sm[i] = __ldg(&Ws5[i]);
    __syncthreads();
    float* xw = sm + F_W + w * 864;

    for (long base = (long)blockIdx.x * 16; base < NODES; base += (long)gridDim.x * 16) {
        long n0 = base + w*2, n1 = n0 + 1;
        bool ok0 = n0 < NODES, ok1 = n1 < NODES;
        const float* t0 = g_t4 + (ok0 ? n0 : 0) * 496;
        const float* t1 = g_t4 + (ok1 ? n1 : 0) * 496;

        float A[2][3], vn[2];
#pragma unroll
        for (int e = 0; e < 2; e++) {
            const float* t = e ? t1 : t0;
            float a0=0.f, a1=0.f, a2=0.f;
#pragma unroll
            for (int i = 0; i < 32; i++) {
                float wt = __ldg(&Wh5[i*32 + lane]);
                a0 = fmaf(t[3*i+0], wt, a0);
                a1 = fmaf(t[3*i+1], wt, a1);
                a2 = fmaf(t[3*i+2], wt, a2);
            }
            A[e][0]=a0; A[e][1]=a1; A[e][2]=a2;
            vn[e] = sqrtf(fmaf(a0,a0,fmaf(a1,a1,a2*a2)) + 1e-8f);
        }
        for (int t = lane; t < 400; t += 32) { xw[t] = t0[96+t]; xw[432+t] = t1[96+t]; }
        xw[400+lane] = vn[0]; xw[832+lane] = vn[1];
        __syncwarp();

        float acc0[4], acc1[4];
        int jc[4];
#pragma unroll
        for (int jj = 0; jj < 4; jj++) {
            int j = jj*32 + lane; jc[jj] = j < 100 ? j : 99;
            float v = __ldg(&bs5[jc[jj]]);
            acc0[jj] = v; acc1[jj] = v;
        }
        const float4* x0 = (const float4*)xw;
        const float4* x1 = (const float4*)(xw + 432);
#pragma unroll 2
        for (int i4 = 0; i4 < 108; i4++) {
            float4 va = x0[i4], vb = x1[i4];
            const float* wr = sm + i4 * 400;
#pragma unroll
            for (int q = 0; q < 4; q++) {
                float fa = f4c(va,q), fb = f4c(vb,q);
                const float* wq = wr + q * 100;
#pragma unroll
                for (int jj = 0; jj < 4; jj++) {
                    float wt = wq[jc[jj]];
                    acc0[jj] = fmaf(fa, wt, acc0[jj]);
                    acc1[jj] = fmaf(fb, wt, acc1[jj]);
                }
            }
        }

        float Bv[2][3];
        const int lc = lane & 15;
#pragma unroll
        for (int e = 0; e < 2; e++) {
            float b0=0.f, b1=0.f, b2=0.f;
#pragma unroll
            for (int hh = 0; hh < 32; hh++) {
                float wt = __ldg(&Wv5[hh*16 + lc]);
                b0 = fmaf(__shfl_sync(0xffffffffu, A[e][0], hh), wt, b0);
                b1 = fmaf(__shfl_sync(0xffffffffu, A[e][1], hh), wt, b1);
                b2 = fmaf(__shfl_sync(0xffffffffu, A[e][2], hh), wt, b2);
            }
            Bv[e][0]=b0; Bv[e][1]=b1; Bv[e][2]=b2;
        }

#pragma unroll
        for (int e = 0; e < 2; e++) {
            bool ok = e ? ok1 : ok0;
            long n = e ? n1 : n0;
            const float* hm = g_hm + (ok ? n : 0) * DIM;
            const float* acc = e ? acc1 : acc0;

            float v0=0.f, v1=0.f, v2=0.f, q=0.f;
            if (lane < 16) {
                v0 = hm[3*lane+0] + Bv[e][0];
                v1 = hm[3*lane+1] + Bv[e][1];
                v2 = hm[3*lane+2] + Bv[e][2];
                q = fmaf(v0,v0,fmaf(v1,v1,v2*v2));
            }
#pragma unroll
            for (int o = 16; o; o >>= 1) q += __shfl_xor_sync(0xffffffffu, q, o);
            float dinv = rsqrtf(q * (1.f/16.f) + 1e-8f);

            float s[4]; float sum = 0.f, sq = 0.f;
#pragma unroll
            for (int jj = 0; jj < 4; jj++) {
                int j = jj*32 + lane;
                s[jj] = (j < 100) ? (hm[48+j] + acc[jj]) : 0.f;
                sum += s[jj]; sq = fmaf(s[jj], s[jj], sq);
            }
#pragma unroll
            for (int o = 16; o; o >>= 1) {
                sum += __shfl_xor_sync(0xffffffffu, sum, o);
                sq  += __shfl_xor_sync(0xffffffffu, sq,  o);
            }
            float mu  = sum * 0.01f;
            float var = sq * 0.01f - mu*mu;
            float inv = rsqrtf(var + 1e-5f);

            if (ok) {
                float m = (float)__ldg(&maskV[n]);
                float* o = out + n * DIM;
                if (lane < 16) {
                    o[3*lane+0] = m * v0 * dinv;
                    o[3*lane+1] = m * v1 * dinv;
                    o[3*lane+2] = m * v2 * dinv;
                }
#pragma unroll
                for (int jj = 0; jj < 4; jj++) {
                    int j = jj*32 + lane;
                    if (j < 100)
                        o[48+j] = m * ((s[jj]-mu)*inv*__ldg(&lng[j]) + __ldg(&lnb[j]));
                }
            }
        }
        __syncwarp();
    }
}

// =================================================================
extern "C" void kernel_launch(void* const* d_in, const int* in_sizes, int n_in,
                              void* d_out, int out_size)
{
    const float* hV    = (const float*)d_in[0];
    const float* hM    = (const float*)d_in[1];
    const int*   maskV = (const int*)  d_in[2];
    const int*   maskA = (const int*)  d_in[3];
    const float* Wh1 = (const float*)d_in[4];
    const float* Wv1 = (const float*)d_in[5];
    const float* Ws1 = (const float*)d_in[6];
    const float* bs1 = (const float*)d_in[7];
    const float* Wh2 = (const float*)d_in[8];
    const float* Wv2 = (const float*)d_in[9];
    const float* Ws2 = (const float*)d_in[10];
    const float* bs2 = (const float*)d_in[11];
    const float* Wh3 = (const float*)d_in[12];
    const float* Wv3 = (const float*)d_in[13];
    const float* Ws3 = (const float*)d_in[14];
    const float* bs3 = (const float*)d_in[15];
    const float* Wh4 = (const float*)d_in[16];
    const float* Wv4 = (const float*)d_in[17];
    const float* Ws4 = (const float*)d_in[18];
    const float* bs4 = (const float*)d_in[19];
    const float* Wh5 = (const float*)d_in[20];
    const float* Wv5 = (const float*)d_in[21];
    const float* Ws5 = (const float*)d_in[22];
    const float* bs5 = (const float*)d_in[23];
    const float* ln0g = (const float*)d_in[24];
    const float* ln0b = (const float*)d_in[25];
    const float* ln1g = (const float*)d_in[26];
    const float* ln1b = (const float*)d_in[27];

    static int attr_done = 0;
    if (!attr_done) {
        cudaFuncSetAttribute(pre_kernel,
                             cudaFuncAttributeMaxDynamicSharedMemorySize, PRE_SMEM);
        cudaFuncSetAttribute(edge_kernel,
                             cudaFuncAttributeMaxDynamicSharedMemorySize, EDGE_SMEM);
        cudaFuncSetAttribute(gvp4_kernel,
                             cudaFuncAttributeMaxDynamicSharedMemorySize, G4_SMEM);
        cudaFuncSetAttribute(final_kernel,
                             cudaFuncAttributeMaxDynamicSharedMemorySize, F_SMEM);
        attr_done = 1;
    }

    pre_kernel <<<148, 256, PRE_SMEM >>>(hV, Wh1, Ws1, bs1);
    edge_kernel<<<148, 512, EDGE_SMEM>>>(hM, maskA, hV, ln0g, ln0b,
                                         Wh1, Wv1, Ws1,
                                         Wh2, Wv2, Ws2, bs2,
                                         Wh3, Wv3, Ws3, bs3);
    gvp4_kernel<<<148, 256, G4_SMEM>>>(Wh4, Wv4, Ws4, bs4);
    final_kernel<<<148, 256, F_SMEM>>>(maskV, Wh5, Wv5, Ws5, bs5, ln1g, ln1b,
                                       (float*)d_out);
}

// round 11
// speedup vs baseline: 1.3287x; 1.0301x over previous
#include <cuda_runtime.h>
#include <cuda_bf16.h>
#include <math.h>

#define BB 2
#define NN 8192
#define KK 30
#define NODES (BB*NN)
#define DIM 148

// ---------------- scratch ----------------
__device__ float g_vhV[NODES * 96];
__device__ float g_sV1[NODES * 100];
__device__ float g_hm [NODES * DIM];
__device__ float g_t4 [NODES * 496];

__device__ __forceinline__ float f4c(const float4& v, int q) {
    return q == 0 ? v.x : q == 1 ? v.y : q == 2 ? v.z : v.w;
}
__device__ __forceinline__ unsigned tf32u(float f) {
    unsigned u;
    asm("cvt.rna.tf32.f32 %0, %1;" : "=r"(u) : "f"(f));
    return u;
}
__device__ __forceinline__ float tf32f(float f) { return __uint_as_float(tf32u(f)); }

__device__ __forceinline__ void mma8(float c[4], const unsigned a[4], unsigned b0, unsigned b1) {
    asm volatile(
        "mma.sync.aligned.m16n8k8.row.col.f32.tf32.tf32.f32 "
        "{%0,%1,%2,%3}, {%4,%5,%6,%7}, {%8,%9}, {%0,%1,%2,%3};"
        : "+f"(c[0]), "+f"(c[1]), "+f"(c[2]), "+f"(c[3])
        : "r"(a[0]), "r"(a[1]), "r"(a[2]), "r"(a[3]), "r"(b0), "r"(b1));
}

// =================================================================
// Kernel 0: per-node precompute
// =================================================================
#define P_W 10000
#define PRE_SMEM ((P_W + 8*200) * 4)

__global__ __launch_bounds__(256, 1)
void pre_kernel(const float* __restrict__ hV,
                const float* __restrict__ Wh1,
                const float* __restrict__ Ws1,
                const float* __restrict__ bs1)
{
    extern __shared__ float sm[];
    const int tid = threadIdx.x, w = tid >> 5, lane = tid & 31;
    for (int i = tid; i < P_W; i += 256) sm[i] = __ldg(&Ws1[i]);
    __syncthreads();
    float* xw = sm + P_W + w * 200;

    for (long base = (long)blockIdx.x * 16; base < NODES; base += (long)gridDim.x * 16) {
        long n0 = base + w * 2, n1 = n0 + 1;
        bool ok0 = n0 < NODES, ok1 = n1 < NODES;
        const float* hv0 = hV + (ok0 ? n0 : 0) * DIM;
        const float* hv1 = hV + (ok1 ? n1 : 0) * DIM;

#pragma unroll
        for (int e = 0; e < 2; e++) {
            const float* hv = e ? hv1 : hv0;
            float a0 = 0.f, a1 = 0.f, a2 = 0.f;
#pragma unroll
            for (int i = 0; i < 16; i++) {
                float wt = __ldg(&Wh1[i * 32 + lane]);
                a0 = fmaf(hv[3*i+0], wt, a0);
                a1 = fmaf(hv[3*i+1], wt, a1);
                a2 = fmaf(hv[3*i+2], wt, a2);
            }
            bool ok = e ? ok1 : ok0;
            long n = e ? n1 : n0;
            if (ok) {
                g_vhV[n*96 + lane*3 + 0] = a0;
                g_vhV[n*96 + lane*3 + 1] = a1;
                g_vhV[n*96 + lane*3 + 2] = a2;
            }
        }

        for (int t = lane; t < 100; t += 32) { xw[t] = hv0[48+t]; xw[100+t] = hv1[48+t]; }
        __syncwarp();

        int jc[4]; float a0[4], a1[4];
#pragma unroll
        for (int jj = 0; jj < 4; jj++) {
            int j = jj*32 + lane; jc[jj] = j < 100 ? j : 99;
            float v = __ldg(&bs1[jc[jj]]);
            a0[jj] = v; a1[jj] = v;
        }
        const float4* x0 = (const float4*)xw;
        const float4* x1 = (const float4*)(xw + 100);
#pragma unroll 2
        for (int i4 = 0; i4 < 25; i4++) {
            float4 va = x0[i4], vb = x1[i4];
            const float* wr = sm + i4 * 400;
#pragma unroll
            for (int q = 0; q < 4; q++) {
                float fa = f4c(va,q), fb = f4c(vb,q);
                const float* wq = wr + q * 100;
#pragma unroll
                for (int jj = 0; jj < 4; jj++) {
                    float wt = wq[jc[jj]];
                    a0[jj] = fmaf(fa, wt, a0[jj]);
                    a1[jj] = fmaf(fb, wt, a1[jj]);
                }
            }
        }
#pragma unroll
        for (int jj = 0; jj < 4; jj++) {
            int j = jj*32 + lane;
            if (j < 100) {
                if (ok0) g_sV1[n0*100 + j] = a0[jj];
                if (ok1) g_sV1[n1*100 + j] = a1[jj];
            }
        }
        __syncwarp();
    }
}

// =================================================================
// Edge kernel: ALL matmuls (s and v) on tf32 mma.sync
// 512 threads = 16 warps; 1 node per CTA iteration.
// =================================================================
#define O_W1    0        // [136][104] tf32 (Ws1 rows 100..231)
#define O_W2    14144    // [120][104]
#define O_W3    26624    // [120][104]
#define O_WH1S  39104    // [16][40]  (Wh1 rows 16..31)
#define O_WV1S  39744    // [32][24]
#define O_WH2S  40512    // [16][24]
#define O_WV2S  40896    // [16][24]
#define O_WH3S  41280    // [16][24]
#define O_WV3S  41664    // [16][24]
#define O_BS2   42048    // 100
#define O_BS3   42148    // 100
#define O_PVH   42248    // 96
#define O_PRS   42344    // 100
#define O_ACC   42444    // 148
#define O_MK    42592    // 32
#define O_VA    42624    // [96][20]  (also VC / VD)
#define O_VB    44544    // [96][36]
#define O_X1    48000    // [32][140] (X3 aliases, stride 124)
#define O_X2    52480    // [32][124]
#define SM_FLOATS 56448
#define EDGE_SMEM (SM_FLOATS * 4)   // 225792 B

#define XS1 140
#define XS2 124
#define WS  104
#define VAS 20
#define VBS 36

// s-stage MMA: warp w (0..6) handles n-tiles {2w, 2w+1(<13)}, m-tiles {0,1}
__device__ __forceinline__ void mma_stage(const unsigned* __restrict__ X, int XS,
                                          const unsigned* __restrict__ Wm, int KT,
                                          int gid, int tig, int w, float C[2][2][4])
{
    const bool nt1ok = (2*w+1) < 13;
    const int col0 = 8*(2*w) + gid;
    const int col1 = nt1ok ? (8*(2*w+1) + gid) : col0;
#pragma unroll 2
    for (int kt = 0; kt < KT; kt++) {
        const int k0 = kt * 8;
        unsigned a[2][4];
#pragma unroll
        for (int mt = 0; mt < 2; mt++) {
            const unsigned* xr = X + (16*mt + gid)*XS + k0 + tig;
            a[mt][0] = xr[0];
            a[mt][1] = xr[8*XS];
            a[mt][2] = xr[4];
            a[mt][3] = xr[8*XS + 4];
        }
        const unsigned* wr = Wm + (k0 + tig)*WS;
        unsigned b00 = wr[col0], b01 = wr[4*WS + col0];
        unsigned b10 = wr[col1], b11 = wr[4*WS + col1];
#pragma unroll
        for (int mt = 0; mt < 2; mt++) {
            mma8(C[mt][0], a[mt], b00, b01);
            if (nt1ok) mma8(C[mt][1], a[mt], b10, b11);
        }
    }
}

__device__ __forceinline__ void store_stage(float* __restrict__ Xo, int XSo,
                                            const float* __restrict__ addend,
                                            const float C[2][2][4],
                                            int gid, int tig, int w)
{
#pragma unroll
    for (int mt = 0; mt < 2; mt++)
#pragma unroll
    for (int nti = 0; nti < 2; nti++) {
        int nt = 2*w + nti;
        if (nt >= 13) continue;
#pragma unroll
        for (int r = 0; r < 4; r++) {
            int edge = 16*mt + gid + ((r >> 1) << 3);
            int n = 8*nt + 2*tig + (r & 1);
            if (edge < 30 && n < 100)
                Xo[edge*XSo + n] = tf32f(fmaxf(C[mt][nti][r] + addend[n], 0.f));
        }
    }
}

// generic single-tile MMA for vector stages
__device__ __forceinline__ void mma_tile(const unsigned* __restrict__ A, int AS,
                                         const unsigned* __restrict__ Bw, int BS,
                                         int KT, int mt, int nt,
                                         int gid, int tig, float C[4])
{
#pragma unroll 2
    for (int kt = 0; kt < KT; kt++) {
        const unsigned* xr = A + (16*mt + gid)*AS + kt*8 + tig;
        unsigned a[4] = { xr[0], xr[8*AS], xr[4], xr[8*AS + 4] };
        const unsigned* wr = Bw + (kt*8 + tig)*BS;
        mma8(C, a, wr[8*nt + gid], wr[4*BS + 8*nt + gid]);
    }
}

__global__ __launch_bounds__(512, 1)
void edge_kernel(const float* __restrict__ hM, const int* __restrict__ maskA,
                 const float* __restrict__ hV,
                 const float* __restrict__ lng, const float* __restrict__ lnb,
                 const float* __restrict__ Wh1, const float* __restrict__ Wv1,
                 const float* __restrict__ Ws1,
                 const float* __restrict__ Wh2, const float* __restrict__ Wv2,
                 const float* __restrict__ Ws2, const float* __restrict__ bs2,
                 const float* __restrict__ Wh3, const float* __restrict__ Wv3,
                 const float* __restrict__ Ws3, const float* __restrict__ bs3)
{
    extern __shared__ float sm[];
    unsigned* usm = (unsigned*)sm;
    const int tid = threadIdx.x, w = tid >> 5, lane = tid & 31;
    const int gid = lane >> 2, tig = lane & 3;

    // ---- one-time fills ----
    for (int i = tid; i < 136*WS; i += 512) {
        int k = i / WS, n = i - k*WS;
        sm[O_W1+i] = (k < 132 && n < 100) ? tf32f(__ldg(&Ws1[(100+k)*100 + n])) : 0.f;
    }
    for (int i = tid; i < 120*WS; i += 512) {
        int k = i / WS, n = i - k*WS;
        sm[O_W2+i] = (k < 116 && n < 100) ? tf32f(__ldg(&Ws2[k*100 + n])) : 0.f;
        sm[O_W3+i] = (k < 116 && n < 100) ? tf32f(__ldg(&Ws3[k*100 + n])) : 0.f;
    }
    for (int i = tid; i < 512; i += 512) {       // Wh1 rows 16..31 -> [16][40]
        int k = i >> 5, n = i & 31;
        sm[O_WH1S + k*40 + n] = tf32f(__ldg(&Wh1[(16+k)*32 + n]));
    }
    if (tid < 512) {                             // Wv1 [32][16] -> stride 24
        int k = tid >> 4, n = tid & 15;
        sm[O_WV1S + k*24 + n] = tf32f(__ldg(&Wv1[k*16 + n]));
    }
    if (tid < 256) {
        int k = tid >> 4, n = tid & 15;
        sm[O_WH2S + k*24 + n] = tf32f(__ldg(&Wh2[tid]));
        sm[O_WV2S + k*24 + n] = tf32f(__ldg(&Wv2[tid]));
        sm[O_WH3S + k*24 + n] = tf32f(__ldg(&Wh3[tid]));
        sm[O_WV3S + k*24 + n] = tf32f(__ldg(&Wv3[tid]));
    }
    if (tid < 100) { sm[O_BS2+tid] = __ldg(&bs2[tid]); sm[O_BS3+tid] = __ldg(&bs3[tid]); }
    // zero X2 fully; X1 stride-140 rows 30,31 and pad cols
    for (int i = tid; i < 32*XS2; i += 512) sm[O_X2+i] = 0.f;
    for (int i = tid; i < 2*XS1;  i += 512) sm[O_X1 + 30*XS1 + i] = 0.f;
    for (int i = tid; i < 30*8;   i += 512) sm[O_X1 + (i>>3)*XS1 + 132 + (i&7)] = 0.f;
    __syncthreads();

    for (int node = blockIdx.x; node < NODES; node += gridDim.x) {
        // ---- P0: stage node + edges ----
        for (int i = tid; i < 148; i += 512) sm[O_ACC+i] = 0.f;
        for (int i = tid; i < 96;  i += 512) sm[O_PVH+i] = g_vhV[(long)node*96  + i];
        for (int i = tid; i < 100; i += 512) sm[O_PRS+i] = g_sV1[(long)node*100 + i];
        if (tid < 30) sm[O_MK+tid] = (float)__ldg(&maskA[(long)node*KK + tid]);
        {
            const float* src = hM + (long)node * KK * DIM;
            for (int idx = tid; idx < KK*DIM; idx += 512) {
                int e = idx / DIM, t = idx - e*DIM;
                float v = __ldg(&src[idx]);
                if (t < 48) sm[O_VA + (3*e + t%3)*VAS + t/3] = tf32f(v);  // vM -> VA[96x16]
                else        sm[O_X1 + e*XS1 + (t-48)] = tf32f(v);        // sM -> X1 cols 0..99
            }
        }
        __syncthreads();

        // ---- P1: vh1 MMA: VB[96x32] = VA @ Wh1s + PVH addend (all warps, 24 tiles)
        for (int t = w; t < 24; t += 16) {
            int mt = t % 6, nt = t / 6;
            float C[4] = {};
            mma_tile(usm + O_VA, VAS, usm + O_WH1S, 40, 2, mt, nt, gid, tig, C);
#pragma unroll
            for (int r = 0; r < 4; r++) {
                int row = 16*mt + gid + 8*(r>>1);
                int n = 8*nt + 2*tig + (r&1);
                sm[O_VB + row*VBS + n] = tf32f(C[r] + sm[O_PVH + n*3 + (row%3)]);
            }
        }
        __syncthreads();

        // ---- P2: vn1 -> X1 cols 100..131
        for (int v = tid; v < 960; v += 512) {
            int e = v >> 5, h = v & 31;
            float x0 = sm[O_VB + (3*e+0)*VBS + h];
            float x1 = sm[O_VB + (3*e+1)*VBS + h];
            float x2 = sm[O_VB + (3*e+2)*VBS + h];
            sm[O_X1 + e*XS1 + 100 + h] = tf32f(sqrtf(fmaf(x0,x0,fmaf(x1,x1,x2*x2)) + 1e-8f));
        }
        __syncthreads();

        // ---- P3: s1 MMA (w<7) || v1 MMA (w>=7): VC = VB @ Wv1s (raw fp32)
        if (w < 7) {
            float C[2][2][4] = {};
            mma_stage(usm + O_X1, XS1, usm + O_W1, 17, gid, tig, w, C);
            store_stage(sm + O_X2, XS2, sm + O_PRS, C, gid, tig, w);
        } else {
            for (int t = w - 7; t < 12; t += 9) {
                int mt = t % 6, nt = t / 6;
                float C[4] = {};
                mma_tile(usm + O_VB, VBS, usm + O_WV1S, 24, 4, mt, nt, gid, tig, C);
#pragma unroll
                for (int r = 0; r < 4; r++) {
                    int row = 16*mt + gid + 8*(r>>1);
                    int n = 8*nt + 2*tig + (r&1);
                    sm[O_VA + row*VAS + n] = C[r];
                }
            }
        }
        __syncthreads();

        // ---- P4: gate v1 in VC (tf32); spare threads zero X3 pads
        if (tid < 480) {
            int e = tid >> 4, h = tid & 15;
            float x0 = sm[O_VA + (3*e+0)*VAS + h];
            float x1 = sm[O_VA + (3*e+1)*VAS + h];
            float x2 = sm[O_VA + (3*e+2)*VAS + h];
            float nr = sqrtf(fmaf(x0,x0,fmaf(x1,x1,x2*x2)) + 1e-8f);
            float g = 1.f / (1.f + __expf(-nr));
            sm[O_VA + (3*e+0)*VAS + h] = tf32f(x0*g);
            sm[O_VA + (3*e+1)*VAS + h] = tf32f(x1*g);
            sm[O_VA + (3*e+2)*VAS + h] = tf32f(x2*g);
        } else {
            for (int i = tid - 480; i < 488; i += 32) {
                if (i < 240) sm[O_X1 + (i>>3)*XS2 + 116 + (i&7)] = 0.f;
                else         sm[O_X1 + 30*XS2 + (i-240)] = 0.f;
            }
        }
        __syncthreads();

        // ---- P5: vh2 MMA: VB[96x16] = VC @ Wh2s (12 tiles)
        for (int t = w; t < 12; t += 16) {
            int mt = t % 6, nt = t / 6;
            float C[4] = {};
            mma_tile(usm + O_VA, VAS, usm + O_WH2S, 24, 2, mt, nt, gid, tig, C);
#pragma unroll
            for (int r = 0; r < 4; r++) {
                int row = 16*mt + gid + 8*(r>>1);
                int n = 8*nt + 2*tig + (r&1);
                sm[O_VB + row*VBS + n] = tf32f(C[r]);
            }
        }
        __syncthreads();

        // ---- P6: vn2 -> X2 cols 100..115
        if (tid < 480) {
            int e = tid >> 4, h = tid & 15;
            float x0 = sm[O_VB + (3*e+0)*VBS + h];
            float x1 = sm[O_VB + (3*e+1)*VBS + h];
            float x2 = sm[O_VB + (3*e+2)*VBS + h];
            sm[O_X2 + e*XS2 + 100 + h] = tf32f(sqrtf(fmaf(x0,x0,fmaf(x1,x1,x2*x2)) + 1e-8f));
        }
        __syncthreads();

        // ---- P7: s2 MMA (w<7) || v2 MMA (w>=7)
        if (w < 7) {
            float C[2][2][4] = {};
            mma_stage(usm + O_X2, XS2, usm + O_W2, 15, gid, tig, w, C);
            store_stage(sm + O_X1, XS2, sm + O_BS2, C, gid, tig, w);   // X3 = X1 space
        } else {
            for (int t = w - 7; t < 12; t += 9) {
                int mt = t % 6, nt = t / 6;
                float C[4] = {};
                mma_tile(usm + O_VB, VBS, usm + O_WV2S, 24, 2, mt, nt, gid, tig, C);
#pragma unroll
                for (int r = 0; r < 4; r++) {
                    int row = 16*mt + gid + 8*(r>>1);
                    int n = 8*nt + 2*tig + (r&1);
                    sm[O_VA + row*VAS + n] = C[r];
                }
            }
        }
        __syncthreads();

        // ---- P8: gate v2 in VC (tf32)
        if (tid < 480) {
            int e = tid >> 4, h = tid & 15;
            float x0 = sm[O_VA + (3*e+0)*VAS + h];
            float x1 = sm[O_VA + (3*e+1)*VAS + h];
            float x2 = sm[O_VA + (3*e+2)*VAS + h];
            float nr = sqrtf(fmaf(x0,x0,fmaf(x1,x1,x2*x2)) + 1e-8f);
            float g = 1.f / (1.f + __expf(-nr));
            sm[O_VA + (3*e+0)*VAS + h] = tf32f(x0*g);
            sm[O_VA + (3*e+1)*VAS + h] = tf32f(x1*g);
            sm[O_VA + (3*e+2)*VAS + h] = tf32f(x2*g);
        }
        __syncthreads();

        // ---- P9: vh3 MMA: VB = VC @ Wh3s
        for (int t = w; t < 12; t += 16) {
            int mt = t % 6, nt = t / 6;
            float C[4] = {};
            mma_tile(usm + O_VA, VAS, usm + O_WH3S, 24, 2, mt, nt, gid, tig, C);
#pragma unroll
            for (int r = 0; r < 4; r++) {
                int row = 16*mt + gid + 8*(r>>1);
                int n = 8*nt + 2*tig + (r&1);
                sm[O_VB + row*VBS + n] = tf32f(C[r]);
            }
        }
        __syncthreads();

        // ---- P10: vn3 -> X3 cols 100..115
        if (tid < 480) {
            int e = tid >> 4, h = tid & 15;
            float x0 = sm[O_VB + (3*e+0)*VBS + h];
            float x1 = sm[O_VB + (3*e+1)*VBS + h];
            float x2 = sm[O_VB + (3*e+2)*VBS + h];
            sm[O_X1 + e*XS2 + 100 + h] = tf32f(sqrtf(fmaf(x0,x0,fmaf(x1,x1,x2*x2)) + 1e-8f));
        }
        __syncthreads();

        // ---- P11: s3 MMA + masked scalar acc (w<7) || v3 MMA -> VD (w>=7)
        if (w < 7) {
            float C[2][2][4] = {};
            mma_stage(usm + O_X1, XS2, usm + O_W3, 15, gid, tig, w, C);
#pragma unroll
            for (int mt = 0; mt < 2; mt++)
#pragma unroll
            for (int nti = 0; nti < 2; nti++) {
                int nt = 2*w + nti;
                if (nt >= 13) continue;
#pragma unroll
                for (int r = 0; r < 4; r++) {
                    int edge = 16*mt + gid + ((r >> 1) << 3);
                    int n = 8*nt + 2*tig + (r & 1);
                    if (edge < 30 && n < 100)
                        atomicAdd(&sm[O_ACC + 48 + n], sm[O_MK + edge] * C[mt][nti][r]);
                }
            }
        } else {
            for (int t = w - 7; t < 12; t += 9) {
                int mt = t % 6, nt = t / 6;
                float C[4] = {};
                mma_tile(usm + O_VB, VBS, usm + O_WV3S, 24, 2, mt, nt, gid, tig, C);
#pragma unroll
                for (int r = 0; r < 4; r++) {
                    int row = 16*mt + gid + 8*(r>>1);
                    int n = 8*nt + 2*tig + (r&1);
                    sm[O_VA + row*VAS + n] = C[r];   // VD raw fp32
                }
            }
        }
        __syncthreads();

        // ---- P12: masked v-reduce: ACC[3h+c] = sum_e mk[e]*VD[(3e+c)][h]
        if (tid < 48) {
            int h = tid / 3, c = tid - 3*h;
            float s = 0.f;
#pragma unroll 5
            for (int e = 0; e < 30; e++)
                s = fmaf(sm[O_MK + e], sm[O_VA + (3*e+c)*VAS + h], s);
            sm[O_ACC + 3*h + c] = s;
        }
        __syncthreads();

        // ---- P13: ln0 on (h_V + mean) -> g_hm
        if (w == 0) {
            float smk = (lane < 30) ? sm[O_MK + lane] : 0.f;
#pragma unroll
            for (int o = 16; o; o >>= 1) smk += __shfl_xor_sync(0xffffffffu, smk, o);

            const float* hv = hV + (long)node * DIM;
            const float inv30 = 1.f / 30.f;
            float v0=0.f, v1=0.f, v2=0.f, q=0.f;
            if (lane < 16) {
                v0 = hv[3*lane+0] + sm[O_ACC + 3*lane+0] * inv30;
                v1 = hv[3*lane+1] + sm[O_ACC + 3*lane+1] * inv30;
                v2 = hv[3*lane+2] + sm[O_ACC + 3*lane+2] * inv30;
                q = fmaf(v0,v0,fmaf(v1,v1,v2*v2));
            }
#pragma unroll
            for (int o = 16; o; o >>= 1) q += __shfl_xor_sync(0xffffffffu, q, o);
            float dinv = rsqrtf(q * (1.f/16.f) + 1e-8f);

            float s[4]; float sum = 0.f, sq = 0.f;
#pragma unroll
            for (int jj = 0; jj < 4; jj++) {
                int j = jj*32 + lane;
                s[jj] = (j < 100)
                    ? (hv[48+j] + (sm[O_ACC + 48 + j] + sm[O_BS3+j]*smk) * inv30) : 0.f;
                sum += s[jj]; sq = fmaf(s[jj], s[jj], sq);
            }
#pragma unroll
            for (int o = 16; o; o >>= 1) {
                sum += __shfl_xor_sync(0xffffffffu, sum, o);
                sq  += __shfl_xor_sync(0xffffffffu, sq,  o);
            }
            float mu  = sum * 0.01f;
            float var = sq * 0.01f - mu*mu;
            float inv = rsqrtf(var + 1e-5f);

            float* o = g_hm + (long)node * DIM;
            if (lane < 16) {
                o[3*lane+0] = v0*dinv; o[3*lane+1] = v1*dinv; o[3*lane+2] = v2*dinv;
            }
#pragma unroll
            for (int jj = 0; jj < 4; jj++) {
                int j = jj*32 + lane;
                if (j < 100) o[48+j] = (s[jj]-mu)*inv*__ldg(&lng[j]) + __ldg(&lnb[j]);
            }
        }
        __syncthreads();
    }
}

// =================================================================
// Kernel 3: gvp4
// =================================================================
#define G4_W 52800
#define G4_SMEM ((G4_W + 8*264) * 4)

__global__ __launch_bounds__(256, 1)
void gvp4_kernel(const float* __restrict__ Wh4, const float* __restrict__ Wv4,
                 const float* __restrict__ Ws4, const float* __restrict__ bs4)
{
    extern __shared__ float sm[];
    const int tid = threadIdx.x, w = tid >> 5, lane = tid & 31;
    for (int i = tid; i < G4_W; i += 256) sm[i] = __ldg(&Ws4[i]);
    __syncthreads();
    float* xw = sm + G4_W + w * 264;

    for (long base = (long)blockIdx.x * 16; base < NODES; base += (long)gridDim.x * 16) {
        long n0 = base + w*2, n1 = n0 + 1;
        bool ok0 = n0 < NODES, ok1 = n1 < NODES;
        const float* h0 = g_hm + (ok0 ? n0 : 0) * DIM;
        const float* h1 = g_hm + (ok1 ? n1 : 0) * DIM;

        float A[2][3], vn[2];
#pragma unroll
        for (int e = 0; e < 2; e++) {
            const float* h = e ? h1 : h0;
            float a0=0.f, a1=0.f, a2=0.f;
#pragma unroll
            for (int i = 0; i < 16; i++) {
                float wt = __ldg(&Wh4[i*32 + lane]);
                a0 = fmaf(h[3*i+0], wt, a0);
                a1 = fmaf(h[3*i+1], wt, a1);
                a2 = fmaf(h[3*i+2], wt, a2);
            }
            A[e][0]=a0; A[e][1]=a1; A[e][2]=a2;
            vn[e] = sqrtf(fmaf(a0,a0,fmaf(a1,a1,a2*a2)) + 1e-8f);
        }
        for (int t = lane; t < 100; t += 32) { xw[t] = h0[48+t]; xw[132+t] = h1[48+t]; }
        xw[100+lane] = vn[0]; xw[232+lane] = vn[1];
        __syncwarp();

        float acc0[13], acc1[13];
        int jm[13];
#pragma unroll
        for (int jj = 0; jj < 13; jj++) {
            int j = lane + jj*32; jm[jj] = j < 400 ? j : 399;
            float v = __ldg(&bs4[jm[jj]]);
            acc0[jj] = v; acc1[jj] = v;
        }
        const float4* x0 = (const float4*)xw;
        const float4* x1 = (const float4*)(xw + 132);
        for (int i4 = 0; i4 < 33; i4++) {
            float4 va = x0[i4], vb = x1[i4];
            const float* wr = sm + i4 * 1600;
#pragma unroll
            for (int q = 0; q < 4; q++) {
                float fa = f4c(va,q), fb = f4c(vb,q);
                const float* wq = wr + q * 400;
#pragma unroll
                for (int jj = 0; jj < 13; jj++) {
                    float wt = wq[jm[jj]];
                    acc0[jj] = fmaf(fa, wt, acc0[jj]);
                    acc1[jj] = fmaf(fb, wt, acc1[jj]);
                }
            }
        }
#pragma unroll
        for (int jj = 0; jj < 13; jj++) {
            acc0[jj] = fmaxf(acc0[jj], 0.f);
            acc1[jj] = fmaxf(acc1[jj], 0.f);
        }

#pragma unroll
        for (int e = 0; e < 2; e++) {
            float b0=0.f, b1=0.f, b2=0.f;
#pragma unroll
            for (int hh = 0; hh < 32; hh++) {
                float wt = __ldg(&Wv4[hh*32 + lane]);
                b0 = fmaf(__shfl_sync(0xffffffffu, A[e][0], hh), wt, b0);
                b1 = fmaf(__shfl_sync(0xffffffffu, A[e][1], hh), wt, b1);
                b2 = fmaf(__shfl_sync(0xffffffffu, A[e][2], hh), wt, b2);
            }
            float nr = sqrtf(fmaf(b0,b0,fmaf(b1,b1,b2*b2)) + 1e-8f);
            float gt = 1.f / (1.f + __expf(-nr));
            bool ok = e ? ok1 : ok0;
            long n = e ? n1 : n0;
            if (ok) {
                float* o = g_t4 + n * 496;
                o[3*lane+0]=b0*gt; o[3*lane+1]=b1*gt; o[3*lane+2]=b2*gt;
                float* acc = e ? acc1 : acc0;
#pragma unroll
                for (int jj = 0; jj < 13; jj++) {
                    int j = lane + jj*32;
                    if (j < 400) o[96+j] = acc[jj];
                }
            }
        }
        __syncwarp();
    }
}

// =================================================================
// Kernel 4: final
// =================================================================
#define F_W 43200
#define F_SMEM ((F_W + 8*864) * 4)

__global__ __launch_bounds__(256, 1)
void final_kernel(const int* __restrict__ maskV,
                  const float* __restrict__ Wh5, const float* __restrict__ Wv5,
                  const float* __restrict__ Ws5, const float* __restrict__ bs5,
                  const float* __restrict__ lng, const float* __restrict__ lnb,
                  float* __restrict__ out)
{
    extern __shared__ float sm[];
    const int tid = threadIdx.x, w = tid >> 5, lane = tid & 31;
    for (int i = tid; i < F_W; i += 256) sm[i] = __ldg(&Ws5[i]);
    __syncthreads();
    float* xw = sm + F_W + w * 864;

    for (long base = (long)blockIdx.x * 16; base < NODES; base += (long)gridDim.x * 16) {
        long n0 = base + w*2, n1 = n0 + 1;
        bool ok0 = n0 < NODES, ok1 = n1 < NODES;
        const float* t0 = g_t4 + (ok0 ? n0 : 0) * 496;
        const float* t1 = g_t4 + (ok1 ? n1 : 0) * 496;

        float A[2][3], vn[2];
#pragma unroll
        for (int e = 0; e < 2; e++) {
            const float* t = e ? t1 : t0;
            float a0=0.f, a1=0.f, a2=0.f;
#pragma unroll
            for (int i = 0; i < 32; i++) {
                float wt = __ldg(&Wh5[i*32 + lane]);
                a0 = fmaf(t[3*i+0], wt, a0);
                a1 = fmaf(t[3*i+1], wt, a1);
                a2 = fmaf(t[3*i+2], wt, a2);
            }
            A[e][0]=a0; A[e][1]=a1; A[e][2]=a2;
            vn[e] = sqrtf(fmaf(a0,a0,fmaf(a1,a1,a2*a2)) + 1e-8f);
        }
        for (int t = lane; t < 400; t += 32) { xw[t] = t0[96+t]; xw[432+t] = t1[96+t]; }
        xw[400+lane] = vn[0]; xw[832+lane] = vn[1];
        __syncwarp();

        float acc0[4], acc1[4];
        int jc[4];
#pragma unroll
        for (int jj = 0; jj < 4; jj++) {
            int j = jj*32 + lane; jc[jj] = j < 100 ? j : 99;
            float v = __ldg(&bs5[jc[jj]]);
            acc0[jj] = v; acc1[jj] = v;
        }
        const float4* x0 = (const float4*)xw;
        const float4* x1 = (const float4*)(xw + 432);
#pragma unroll 2
        for (int i4 = 0; i4 < 108; i4++) {
            float4 va = x0[i4], vb = x1[i4];
            const float* wr = sm + i4 * 400;
#pragma unroll
            for (int q = 0; q < 4; q++) {
                float fa = f4c(va,q), fb = f4c(vb,q);
                const float* wq = wr + q * 100;
#pragma unroll
                for (int jj = 0; jj < 4; jj++) {
                    float wt = wq[jc[jj]];
                    acc0[jj] = fmaf(fa, wt, acc0[jj]);
                    acc1[jj] = fmaf(fb, wt, acc1[jj]);
                }
            }
        }

        float Bv[2][3];
        const int lc = lane & 15;
#pragma unroll
        for (int e = 0; e < 2; e++) {
            float b0=0.f, b1=0.f, b2=0.f;
#pragma unroll
            for (int hh = 0; hh < 32; hh++) {
                float wt = __ldg(&Wv5[hh*16 + lc]);
                b0 = fmaf(__shfl_sync(0xffffffffu, A[e][0], hh), wt, b0);
                b1 = fmaf(__shfl_sync(0xffffffffu, A[e][1], hh), wt, b1);
                b2 = fmaf(__shfl_sync(0xffffffffu, A[e][2], hh), wt, b2);
            }
            Bv[e][0]=b0; Bv[e][1]=b1; Bv[e][2]=b2;
        }

#pragma unroll
        for (int e = 0; e < 2; e++) {
            bool ok = e ? ok1 : ok0;
            long n = e ? n1 : n0;
            const float* hm = g_hm + (ok ? n : 0) * DIM;
            const float* acc = e ? acc1 : acc0;

            float v0=0.f, v1=0.f, v2=0.f, q=0.f;
            if (lane < 16) {
                v0 = hm[3*lane+0] + Bv[e][0];
                v1 = hm[3*lane+1] + Bv[e][1];
                v2 = hm[3*lane+2] + Bv[e][2];
                q = fmaf(v0,v0,fmaf(v1,v1,v2*v2));
            }
#pragma unroll
            for (int o = 16; o; o >>= 1) q += __shfl_xor_sync(0xffffffffu, q, o);
            float dinv = rsqrtf(q * (1.f/16.f) + 1e-8f);

            float s[4]; float sum = 0.f, sq = 0.f;
#pragma unroll
            for (int jj = 0; jj < 4; jj++) {
                int j = jj*32 + lane;
                s[jj] = (j < 100) ? (hm[48+j] + acc[jj]) : 0.f;
                sum += s[jj]; sq = fmaf(s[jj], s[jj], sq);
            }
#pragma unroll
            for (int o = 16; o; o >>= 1) {
                sum += __shfl_xor_sync(0xffffffffu, sum, o);
                sq  += __shfl_xor_sync(0xffffffffu, sq,  o);
            }
            float mu  = sum * 0.01f;
            float var = sq * 0.01f - mu*mu;
            float inv = rsqrtf(var + 1e-5f);

            if (ok) {
                float m = (float)__ldg(&maskV[n]);
                float* o = out + n * DIM;
                if (lane < 16) {
                    o[3*lane+0] = m * v0 * dinv;
                    o[3*lane+1] = m * v1 * dinv;
                    o[3*lane+2] = m * v2 * dinv;
                }
#pragma unroll
                for (int jj = 0; jj < 4; jj++) {
                    int j = jj*32 + lane;
                    if (j < 100)
                        o[48+j] = m * ((s[jj]-mu)*inv*__ldg(&lng[j]) + __ldg(&lnb[j]));
                }
            }
        }
        __syncwarp();
    }
}

// =================================================================
extern "C" void kernel_launch(void* const* d_in, const int* in_sizes, int n_in,
                              void* d_out, int out_size)
{
    const float* hV    = (const float*)d_in[0];
    const float* hM    = (const float*)d_in[1];
    const int*   maskV = (const int*)  d_in[2];
    const int*   maskA = (const int*)  d_in[3];
    const float* Wh1 = (const float*)d_in[4];
    const float* Wv1 = (const float*)d_in[5];
    const float* Ws1 = (const float*)d_in[6];
    const float* bs1 = (const float*)d_in[7];
    const float* Wh2 = (const float*)d_in[8];
    const float* Wv2 = (const float*)d_in[9];
    const float* Ws2 = (const float*)d_in[10];
    const float* bs2 = (const float*)d_in[11];
    const float* Wh3 = (const float*)d_in[12];
    const float* Wv3 = (const float*)d_in[13];
    const float* Ws3 = (const float*)d_in[14];
    const float* bs3 = (const float*)d_in[15];
    const float* Wh4 = (const float*)d_in[16];
    const float* Wv4 = (const float*)d_in[17];
    const float* Ws4 = (const float*)d_in[18];
    const float* bs4 = (const float*)d_in[19];
    const float* Wh5 = (const float*)d_in[20];
    const float* Wv5 = (const float*)d_in[21];
    const float* Ws5 = (const float*)d_in[22];
    const float* bs5 = (const float*)d_in[23];
    const float* ln0g = (const float*)d_in[24];
    const float* ln0b = (const float*)d_in[25];
    const float* ln1g = (const float*)d_in[26];
    const float* ln1b = (const float*)d_in[27];

    static int attr_done = 0;
    if (!attr_done) {
        cudaFuncSetAttribute(pre_kernel,
                             cudaFuncAttributeMaxDynamicSharedMemorySize, PRE_SMEM);
        cudaFuncSetAttribute(edge_kernel,
                             cudaFuncAttributeMaxDynamicSharedMemorySize, EDGE_SMEM);
        cudaFuncSetAttribute(gvp4_kernel,
                             cudaFuncAttributeMaxDynamicSharedMemorySize, G4_SMEM);
        cudaFuncSetAttribute(final_kernel,
                             cudaFuncAttributeMaxDynamicSharedMemorySize, F_SMEM);
        attr_done = 1;
    }

    pre_kernel <<<148, 256, PRE_SMEM >>>(hV, Wh1, Ws1, bs1);
    edge_kernel<<<148, 512, EDGE_SMEM>>>(hM, maskA, hV, ln0g, ln0b,
                                         Wh1, Wv1, Ws1,
                                         Wh2, Wv2, Ws2, bs2,
                                         Wh3, Wv3, Ws3, bs3);
    gvp4_kernel<<<148, 256, G4_SMEM>>>(Wh4, Wv4, Ws4, bs4);
    final_kernel<<<148, 256, F_SMEM>>>(maskV, Wh5, Wv5, Ws5, bs5, ln1g, ln1b,
                                       (float*)d_out);
}

// round 12
// speedup vs baseline: 2.5209x; 1.8973x over previous
#include <cuda_runtime.h>
#include <cuda_bf16.h>
#include <math.h>

#define BB 2
#define NN 8192
#define KK 30
#define NODES (BB*NN)
#define DIM 148

// ---------------- scratch ----------------
__device__ float g_vhV[NODES * 96];
__device__ float g_sV1[NODES * 100];
__device__ float g_hm [NODES * DIM];
__device__ float g_t4 [NODES * 496];

__device__ __forceinline__ float f4c(const float4& v, int q) {
    return q == 0 ? v.x : q == 1 ? v.y : q == 2 ? v.z : v.w;
}
__device__ __forceinline__ unsigned tf32u(float f) {
    unsigned u;
    asm("cvt.rna.tf32.f32 %0, %1;" : "=r"(u) : "f"(f));
    return u;
}
__device__ __forceinline__ float tf32f(float f) { return __uint_as_float(tf32u(f)); }

__device__ __forceinline__ void mma8(float c[4], const unsigned a[4], unsigned b0, unsigned b1) {
    asm volatile(
        "mma.sync.aligned.m16n8k8.row.col.f32.tf32.tf32.f32 "
        "{%0,%1,%2,%3}, {%4,%5,%6,%7}, {%8,%9}, {%0,%1,%2,%3};"
        : "+f"(c[0]), "+f"(c[1]), "+f"(c[2]), "+f"(c[3])
        : "r"(a[0]), "r"(a[1]), "r"(a[2]), "r"(a[3]), "r"(b0), "r"(b1));
}

// =================================================================
// Kernel 0: per-node precompute
// =================================================================
#define P_W 10000
#define PRE_SMEM ((P_W + 8*200) * 4)

__global__ __launch_bounds__(256, 1)
void pre_kernel(const float* __restrict__ hV,
                const float* __restrict__ Wh1,
                const float* __restrict__ Ws1,
                const float* __restrict__ bs1)
{
    extern __shared__ float sm[];
    const int tid = threadIdx.x, w = tid >> 5, lane = tid & 31;
    for (int i = tid; i < P_W; i += 256) sm[i] = __ldg(&Ws1[i]);
    __syncthreads();
    float* xw = sm + P_W + w * 200;

    for (long base = (long)blockIdx.x * 16; base < NODES; base += (long)gridDim.x * 16) {
        long n0 = base + w * 2, n1 = n0 + 1;
        bool ok0 = n0 < NODES, ok1 = n1 < NODES;
        const float* hv0 = hV + (ok0 ? n0 : 0) * DIM;
        const float* hv1 = hV + (ok1 ? n1 : 0) * DIM;

#pragma unroll
        for (int e = 0; e < 2; e++) {
            const float* hv = e ? hv1 : hv0;
            float a0 = 0.f, a1 = 0.f, a2 = 0.f;
#pragma unroll
            for (int i = 0; i < 16; i++) {
                float wt = __ldg(&Wh1[i * 32 + lane]);
                a0 = fmaf(hv[3*i+0], wt, a0);
                a1 = fmaf(hv[3*i+1], wt, a1);
                a2 = fmaf(hv[3*i+2], wt, a2);
            }
            bool ok = e ? ok1 : ok0;
            long n = e ? n1 : n0;
            if (ok) {
                g_vhV[n*96 + lane*3 + 0] = a0;
                g_vhV[n*96 + lane*3 + 1] = a1;
                g_vhV[n*96 + lane*3 + 2] = a2;
            }
        }

        for (int t = lane; t < 100; t += 32) { xw[t] = hv0[48+t]; xw[100+t] = hv1[48+t]; }
        __syncwarp();

        int jc[4]; float a0[4], a1[4];
#pragma unroll
        for (int jj = 0; jj < 4; jj++) {
            int j = jj*32 + lane; jc[jj] = j < 100 ? j : 99;
            float v = __ldg(&bs1[jc[jj]]);
            a0[jj] = v; a1[jj] = v;
        }
        const float4* x0 = (const float4*)xw;
        const float4* x1 = (const float4*)(xw + 100);
#pragma unroll 2
        for (int i4 = 0; i4 < 25; i4++) {
            float4 va = x0[i4], vb = x1[i4];
            const float* wr = sm + i4 * 400;
#pragma unroll
            for (int q = 0; q < 4; q++) {
                float fa = f4c(va,q), fb = f4c(vb,q);
                const float* wq = wr + q * 100;
#pragma unroll
                for (int jj = 0; jj < 4; jj++) {
                    float wt = wq[jc[jj]];
                    a0[jj] = fmaf(fa, wt, a0[jj]);
                    a1[jj] = fmaf(fb, wt, a1[jj]);
                }
            }
        }
#pragma unroll
        for (int jj = 0; jj < 4; jj++) {
            int j = jj*32 + lane;
            if (j < 100) {
                if (ok0) g_sV1[n0*100 + j] = a0[jj];
                if (ok1) g_sV1[n1*100 + j] = a1[jj];
            }
        }
        __syncwarp();
    }
}

// =================================================================
// Edge kernel: tf32 MMA stages 1-2, LINEARIZED stage 3, prefetch
// 512 threads = 16 warps; 1 node per CTA iteration.
// =================================================================
#define O_W1    0        // [136][104] tf32 (Ws1 rows 100..231)
#define O_W2    14144    // [120][104]
#define O_W3    26624    // [120][104]
#define O_WH1S  39104    // [16][40]  (Wh1 rows 16..31)
#define O_WV1S  39744    // [32][24]
#define O_WH2S  40512    // [16][24]
#define O_WV2S  40896    // [16][24]
#define O_WH3S  41280    // [16][24]
#define O_WV3S  41664    // [16][24]
#define O_BS2   42048    // 100
#define O_BS3   42148    // 100
#define O_PVH   42248    // 96
#define O_PRS   42344    // 100
#define O_ACC   42444    // 148
#define O_MK    42592    // 32
#define O_VA    42624    // [96][20]  (also VC)
#define O_VB    44544    // [96][36]
#define O_X1    48000    // [32][140] (X3 aliases, stride 124)
#define O_X2    52480    // [32][124] (z/zv reuse after s2)
#define O_HV    56448    // 148 (prefetched h_V row)
#define SM_FLOATS 56596
#define EDGE_SMEM (SM_FLOATS * 4)   // 226,384 B

#define XS1 140
#define XS2 124
#define WS  104
#define VAS 20
#define VBS 36

// s-stage MMA: warp w (0..6) handles n-tiles {2w, 2w+1(<13)}, m-tiles {0,1}
__device__ __forceinline__ void mma_stage(const unsigned* __restrict__ X, int XS,
                                          const unsigned* __restrict__ Wm, int KT,
                                          int gid, int tig, int w, float C[2][2][4])
{
    const bool nt1ok = (2*w+1) < 13;
    const int col0 = 8*(2*w) + gid;
    const int col1 = nt1ok ? (8*(2*w+1) + gid) : col0;
#pragma unroll 2
    for (int kt = 0; kt < KT; kt++) {
        const int k0 = kt * 8;
        unsigned a[2][4];
#pragma unroll
        for (int mt = 0; mt < 2; mt++) {
            const unsigned* xr = X + (16*mt + gid)*XS + k0 + tig;
            a[mt][0] = xr[0];
            a[mt][1] = xr[8*XS];
            a[mt][2] = xr[4];
            a[mt][3] = xr[8*XS + 4];
        }
        const unsigned* wr = Wm + (k0 + tig)*WS;
        unsigned b00 = wr[col0], b01 = wr[4*WS + col0];
        unsigned b10 = wr[col1], b11 = wr[4*WS + col1];
#pragma unroll
        for (int mt = 0; mt < 2; mt++) {
            mma8(C[mt][0], a[mt], b00, b01);
            if (nt1ok) mma8(C[mt][1], a[mt], b10, b11);
        }
    }
}

__device__ __forceinline__ void store_stage(float* __restrict__ Xo, int XSo,
                                            const float* __restrict__ addend,
                                            const float C[2][2][4],
                                            int gid, int tig, int w)
{
#pragma unroll
    for (int mt = 0; mt < 2; mt++)
#pragma unroll
    for (int nti = 0; nti < 2; nti++) {
        int nt = 2*w + nti;
        if (nt >= 13) continue;
#pragma unroll
        for (int r = 0; r < 4; r++) {
            int edge = 16*mt + gid + ((r >> 1) << 3);
            int n = 8*nt + 2*tig + (r & 1);
            if (edge < 30 && n < 100)
                Xo[edge*XSo + n] = tf32f(fmaxf(C[mt][nti][r] + addend[n], 0.f));
        }
    }
}

// generic single-tile MMA for vector stages
__device__ __forceinline__ void mma_tile(const unsigned* __restrict__ A, int AS,
                                         const unsigned* __restrict__ Bw, int BS,
                                         int KT, int mt, int nt,
                                         int gid, int tig, float C[4])
{
#pragma unroll 2
    for (int kt = 0; kt < KT; kt++) {
        const unsigned* xr = A + (16*mt + gid)*AS + kt*8 + tig;
        unsigned a[4] = { xr[0], xr[8*AS], xr[4], xr[8*AS + 4] };
        const unsigned* wr = Bw + (kt*8 + tig)*BS;
        mma8(C, a, wr[8*nt + gid], wr[4*BS + 8*nt + gid]);
    }
}

__global__ __launch_bounds__(512, 1)
void edge_kernel(const float* __restrict__ hM, const int* __restrict__ maskA,
                 const float* __restrict__ hV,
                 const float* __restrict__ lng, const float* __restrict__ lnb,
                 const float* __restrict__ Wh1, const float* __restrict__ Wv1,
                 const float* __restrict__ Ws1,
                 const float* __restrict__ Wh2, const float* __restrict__ Wv2,
                 const float* __restrict__ Ws2, const float* __restrict__ bs2,
                 const float* __restrict__ Wh3, const float* __restrict__ Wv3,
                 const float* __restrict__ Ws3, const float* __restrict__ bs3)
{
    extern __shared__ float sm[];
    unsigned* usm = (unsigned*)sm;
    const int tid = threadIdx.x, w = tid >> 5, lane = tid & 31;
    const int gid = lane >> 2, tig = lane & 3;

    // ---- one-time weight fills ----
    for (int i = tid; i < 136*WS; i += 512) {
        int k = i / WS, n = i - k*WS;
        sm[O_W1+i] = (k < 132 && n < 100) ? tf32f(__ldg(&Ws1[(100+k)*100 + n])) : 0.f;
    }
    for (int i = tid; i < 120*WS; i += 512) {
        int k = i / WS, n = i - k*WS;
        sm[O_W2+i] = (k < 116 && n < 100) ? tf32f(__ldg(&Ws2[k*100 + n])) : 0.f;
        sm[O_W3+i] = (k < 116 && n < 100) ? tf32f(__ldg(&Ws3[k*100 + n])) : 0.f;
    }
    for (int i = tid; i < 512; i += 512) {
        int k = i >> 5, n = i & 31;
        sm[O_WH1S + k*40 + n] = tf32f(__ldg(&Wh1[(16+k)*32 + n]));
    }
    if (tid < 512) {
        int k = tid >> 4, n = tid & 15;
        sm[O_WV1S + k*24 + n] = tf32f(__ldg(&Wv1[k*16 + n]));
    }
    if (tid < 256) {
        int k = tid >> 4, n = tid & 15;
        sm[O_WH2S + k*24 + n] = tf32f(__ldg(&Wh2[tid]));
        sm[O_WV2S + k*24 + n] = tf32f(__ldg(&Wv2[tid]));
        sm[O_WH3S + k*24 + n] = tf32f(__ldg(&Wh3[tid]));
        sm[O_WV3S + k*24 + n] = tf32f(__ldg(&Wv3[tid]));
    }
    if (tid < 100) { sm[O_BS2+tid] = __ldg(&bs2[tid]); sm[O_BS3+tid] = __ldg(&bs3[tid]); }
    // one-time zeroing: X2 fully; X1(140) rows 30,31 and pad cols 132..139
    for (int i = tid; i < 32*XS2; i += 512) sm[O_X2+i] = 0.f;
    for (int i = tid; i < 2*XS1;  i += 512) sm[O_X1 + 30*XS1 + i] = 0.f;
    for (int i = tid; i < 30*8;   i += 512) sm[O_X1 + (i>>3)*XS1 + 132 + (i&7)] = 0.f;

    // ---- prefetch setup ----
    int soff[9]; bool sval[9];
#pragma unroll
    for (int r = 0; r < 9; r++) {
        int idx = tid + r*512;
        sval[r] = idx < KK*DIM;
        int ii = sval[r] ? idx : 0;
        int e = ii / DIM, t = ii - e*DIM;
        soff[r] = (t < 48) ? (O_VA + (3*e + t%3)*VAS + t/3)
                           : (O_X1 + e*XS1 + (t-48));
    }
    float R[9]; int mkR = 0; float pvhR = 0.f, prsR = 0.f, hvR = 0.f;

    {   // prologue prefetch for first node
        long n = blockIdx.x;
        const float* src = hM + n*KK*DIM;
#pragma unroll
        for (int r = 0; r < 9; r++) if (sval[r]) R[r] = __ldg(&src[tid + r*512]);
        if (tid < 30)  mkR  = __ldg(&maskA[n*KK + tid]);
        if (tid < 96)  pvhR = g_vhV[n*96 + tid];
        if (tid < 100) prsR = g_sV1[n*100 + tid];
        if (tid < 148) hvR  = __ldg(&hV[n*DIM + tid]);
    }
    __syncthreads();

    for (long node = blockIdx.x; node < NODES; node += gridDim.x) {
        // ---- P0: scatter prefetched data (no gmem latency) ----
#pragma unroll
        for (int r = 0; r < 9; r++) if (sval[r]) sm[soff[r]] = tf32f(R[r]);
        if (tid < 30)  sm[O_MK + tid]  = (float)mkR;
        if (tid < 96)  sm[O_PVH + tid] = pvhR;
        if (tid < 100) sm[O_PRS + tid] = prsR;
        if (tid < 148) sm[O_HV + tid]  = hvR;
        __syncthreads();

        // issue prefetch for next node (completes during compute)
        {
            long nn = node + gridDim.x;
            long n = (nn < NODES) ? nn : node;
            const float* src = hM + n*KK*DIM;
#pragma unroll
            for (int r = 0; r < 9; r++) if (sval[r]) R[r] = __ldg(&src[tid + r*512]);
            if (tid < 30)  mkR  = __ldg(&maskA[n*KK + tid]);
            if (tid < 96)  pvhR = g_vhV[n*96 + tid];
            if (tid < 100) prsR = g_sV1[n*100 + tid];
            if (tid < 148) hvR  = __ldg(&hV[n*DIM + tid]);
        }

        // ---- P1: vh1 MMA: VB[96x32] = VA @ Wh1s + PVH addend (24 tiles)
        for (int t = w; t < 24; t += 16) {
            int mt = t % 6, nt = t / 6;
            float C[4] = {};
            mma_tile(usm + O_VA, VAS, usm + O_WH1S, 40, 2, mt, nt, gid, tig, C);
#pragma unroll
            for (int r = 0; r < 4; r++) {
                int row = 16*mt + gid + 8*(r>>1);
                int n = 8*nt + 2*tig + (r&1);
                sm[O_VB + row*VBS + n] = tf32f(C[r] + sm[O_PVH + n*3 + (row%3)]);
            }
        }
        __syncthreads();

        // ---- P2: vn1 -> X1 cols 100..131
        for (int v = tid; v < 960; v += 512) {
            int e = v >> 5, h = v & 31;
            float x0 = sm[O_VB + (3*e+0)*VBS + h];
            float x1 = sm[O_VB + (3*e+1)*VBS + h];
            float x2 = sm[O_VB + (3*e+2)*VBS + h];
            sm[O_X1 + e*XS1 + 100 + h] = tf32f(sqrtf(fmaf(x0,x0,fmaf(x1,x1,x2*x2)) + 1e-8f));
        }
        __syncthreads();

        // ---- P3: s1 MMA (w<7) || v1 MMA (w>=7): VC = VB @ Wv1s
        if (w < 7) {
            float C[2][2][4] = {};
            mma_stage(usm + O_X1, XS1, usm + O_W1, 17, gid, tig, w, C);
            store_stage(sm + O_X2, XS2, sm + O_PRS, C, gid, tig, w);
        } else {
            for (int t = w - 7; t < 12; t += 9) {
                int mt = t % 6, nt = t / 6;
                float C[4] = {};
                mma_tile(usm + O_VB, VBS, usm + O_WV1S, 24, 4, mt, nt, gid, tig, C);
#pragma unroll
                for (int r = 0; r < 4; r++) {
                    int row = 16*mt + gid + 8*(r>>1);
                    int n = 8*nt + 2*tig + (r&1);
                    sm[O_VA + row*VAS + n] = C[r];
                }
            }
        }
        __syncthreads();

        // ---- P4: gate v1 in VC (tf32)
        if (tid < 480) {
            int e = tid >> 4, h = tid & 15;
            float x0 = sm[O_VA + (3*e+0)*VAS + h];
            float x1 = sm[O_VA + (3*e+1)*VAS + h];
            float x2 = sm[O_VA + (3*e+2)*VAS + h];
            float nr = sqrtf(fmaf(x0,x0,fmaf(x1,x1,x2*x2)) + 1e-8f);
            float g = 1.f / (1.f + __expf(-nr));
            sm[O_VA + (3*e+0)*VAS + h] = tf32f(x0*g);
            sm[O_VA + (3*e+1)*VAS + h] = tf32f(x1*g);
            sm[O_VA + (3*e+2)*VAS + h] = tf32f(x2*g);
        }
        __syncthreads();

        // ---- P5: vh2 MMA: VB[96x16] = VC @ Wh2s (12 tiles)
        for (int t = w; t < 12; t += 16) {
            int mt = t % 6, nt = t / 6;
            float C[4] = {};
            mma_tile(usm + O_VA, VAS, usm + O_WH2S, 24, 2, mt, nt, gid, tig, C);
#pragma unroll
            for (int r = 0; r < 4; r++) {
                int row = 16*mt + gid + 8*(r>>1);
                int n = 8*nt + 2*tig + (r&1);
                sm[O_VB + row*VBS + n] = tf32f(C[r]);
            }
        }
        __syncthreads();

        // ---- P6: vn2 -> X2 cols 100..115
        if (tid < 480) {
            int e = tid >> 4, h = tid & 15;
            float x0 = sm[O_VB + (3*e+0)*VBS + h];
            float x1 = sm[O_VB + (3*e+1)*VBS + h];
            float x2 = sm[O_VB + (3*e+2)*VBS + h];
            sm[O_X2 + e*XS2 + 100 + h] = tf32f(sqrtf(fmaf(x0,x0,fmaf(x1,x1,x2*x2)) + 1e-8f));
        }
        __syncthreads();

        // ---- P7: s2 MMA (w<7) || v2 MMA (w>=7)
        if (w < 7) {
            float C[2][2][4] = {};
            mma_stage(usm + O_X2, XS2, usm + O_W2, 15, gid, tig, w, C);
            store_stage(sm + O_X1, XS2, sm + O_BS2, C, gid, tig, w);   // X3 = X1 space
        } else {
            for (int t = w - 7; t < 12; t += 9) {
                int mt = t % 6, nt = t / 6;
                float C[4] = {};
                mma_tile(usm + O_VB, VBS, usm + O_WV2S, 24, 2, mt, nt, gid, tig, C);
#pragma unroll
                for (int r = 0; r < 4; r++) {
                    int row = 16*mt + gid + 8*(r>>1);
                    int n = 8*nt + 2*tig + (r&1);
                    sm[O_VA + row*VAS + n] = C[r];
                }
            }
        }
        __syncthreads();

        // ---- P8: gate v2 in VC (tf32)
        if (tid < 480) {
            int e = tid >> 4, h = tid & 15;
            float x0 = sm[O_VA + (3*e+0)*VAS + h];
            float x1 = sm[O_VA + (3*e+1)*VAS + h];
            float x2 = sm[O_VA + (3*e+2)*VAS + h];
            float nr = sqrtf(fmaf(x0,x0,fmaf(x1,x1,x2*x2)) + 1e-8f);
            float g = 1.f / (1.f + __expf(-nr));
            sm[O_VA + (3*e+0)*VAS + h] = tf32f(x0*g);
            sm[O_VA + (3*e+1)*VAS + h] = tf32f(x1*g);
            sm[O_VA + (3*e+2)*VAS + h] = tf32f(x2*g);
        }
        __syncthreads();

        // ---- P9: vh3 MMA: VB = VC @ Wh3s
        for (int t = w; t < 12; t += 16) {
            int mt = t % 6, nt = t / 6;
            float C[4] = {};
            mma_tile(usm + O_VA, VAS, usm + O_WH3S, 24, 2, mt, nt, gid, tig, C);
#pragma unroll
            for (int r = 0; r < 4; r++) {
                int row = 16*mt + gid + 8*(r>>1);
                int n = 8*nt + 2*tig + (r&1);
                sm[O_VB + row*VBS + n] = tf32f(C[r]);
            }
        }
        __syncthreads();

        // ---- P10: vn3 -> X3 cols 100..115
        if (tid < 480) {
            int e = tid >> 4, h = tid & 15;
            float x0 = sm[O_VB + (3*e+0)*VBS + h];
            float x1 = sm[O_VB + (3*e+1)*VBS + h];
            float x2 = sm[O_VB + (3*e+2)*VBS + h];
            sm[O_X1 + e*XS2 + 100 + h] = tf32f(sqrtf(fmaf(x0,x0,fmaf(x1,x1,x2*x2)) + 1e-8f));
        }
        __syncthreads();

        // ---- P11: LINEARIZED stage 3 — masked sums (no MMAs, no atomics)
        // z[k]   = sum_e mk[e] * X3[e][k]      (k < 116)
        // zv[hc] = sum_e mk[e] * VB[3e+c][h]   (48 values)
        if (tid < 116) {
            float s = 0.f;
#pragma unroll 5
            for (int e = 0; e < 30; e++)
                s = fmaf(sm[O_MK + e], sm[O_X1 + e*XS2 + tid], s);
            sm[O_X2 + tid] = s;
        } else if (tid >= 128 && tid < 176) {
            int i = tid - 128;
            int h = i / 3, c = i - 3*h;
            float s = 0.f;
#pragma unroll 5
            for (int e = 0; e < 30; e++)
                s = fmaf(sm[O_MK + e], sm[O_VB + (3*e+c)*VBS + h], s);
            sm[O_X2 + 128 + i] = s;
        }
        __syncthreads();

        // ---- P12: tiny matvecs: ACC_s = z @ W3 ; ACC_v = zv @ Wv3
        if (tid < 100) {
            float acc = 0.f;
#pragma unroll 4
            for (int k = 0; k < 116; k++)
                acc = fmaf(sm[O_X2 + k], sm[O_W3 + k*WS + tid], acc);
            sm[O_ACC + 48 + tid] = acc;
        } else if (tid >= 128 && tid < 176) {
            int i = tid - 128;
            int o = i / 3, c = i - 3*o;
            float acc = 0.f;
#pragma unroll
            for (int h = 0; h < 16; h++)
                acc = fmaf(sm[O_X2 + 128 + h*3 + c], sm[O_WV3S + h*24 + o], acc);
            sm[O_ACC + 3*o + c] = acc;
        }
        __syncthreads();

        // ---- P13: ln0 on (h_V + mean) -> g_hm  (h_V from prefetched smem)
        if (w == 0) {
            float smk = (lane < 30) ? sm[O_MK + lane] : 0.f;
#pragma unroll
            for (int o = 16; o; o >>= 1) smk += __shfl_xor_sync(0xffffffffu, smk, o);

            const float inv30 = 1.f / 30.f;
            float v0=0.f, v1=0.f, v2=0.f, q=0.f;
            if (lane < 16) {
                v0 = sm[O_HV + 3*lane+0] + sm[O_ACC + 3*lane+0] * inv30;
                v1 = sm[O_HV + 3*lane+1] + sm[O_ACC + 3*lane+1] * inv30;
                v2 = sm[O_HV + 3*lane+2] + sm[O_ACC + 3*lane+2] * inv30;
                q = fmaf(v0,v0,fmaf(v1,v1,v2*v2));
            }
#pragma unroll
            for (int o = 16; o; o >>= 1) q += __shfl_xor_sync(0xffffffffu, q, o);
            float dinv = rsqrtf(q * (1.f/16.f) + 1e-8f);

            float s[4]; float sum = 0.f, sq = 0.f;
#pragma unroll
            for (int jj = 0; jj < 4; jj++) {
                int j = jj*32 + lane;
                s[jj] = (j < 100)
                    ? (sm[O_HV + 48+j] + (sm[O_ACC + 48 + j] + sm[O_BS3+j]*smk) * inv30) : 0.f;
                sum += s[jj]; sq = fmaf(s[jj], s[jj], sq);
            }
#pragma unroll
            for (int o = 16; o; o >>= 1) {
                sum += __shfl_xor_sync(0xffffffffu, sum, o);
                sq  += __shfl_xor_sync(0xffffffffu, sq,  o);
            }
            float mu  = sum * 0.01f;
            float var = sq * 0.01f - mu*mu;
            float inv = rsqrtf(var + 1e-5f);

            float* o = g_hm + (long)node * DIM;
            if (lane < 16) {
                o[3*lane+0] = v0*dinv; o[3*lane+1] = v1*dinv; o[3*lane+2] = v2*dinv;
            }
#pragma unroll
            for (int jj = 0; jj < 4; jj++) {
                int j = jj*32 + lane;
                if (j < 100) o[48+j] = (s[jj]-mu)*inv*__ldg(&lng[j]) + __ldg(&lnb[j]);
            }
        }
        __syncthreads();
    }
}

// =================================================================
// Kernel 3: gvp4
// =================================================================
#define G4_W 52800
#define G4_SMEM ((G4_W + 8*264) * 4)

__global__ __launch_bounds__(256, 1)
void gvp4_kernel(const float* __restrict__ Wh4, const float* __restrict__ Wv4,
                 const float* __restrict__ Ws4, const float* __restrict__ bs4)
{
    extern __shared__ float sm[];
    const int tid = threadIdx.x, w = tid >> 5, lane = tid & 31;
    for (int i = tid; i < G4_W; i += 256) sm[i] = __ldg(&Ws4[i]);
    __syncthreads();
    float* xw = sm + G4_W + w * 264;

    for (long base = (long)blockIdx.x * 16; base < NODES; base += (long)gridDim.x * 16) {
        long n0 = base + w*2, n1 = n0 + 1;
        bool ok0 = n0 < NODES, ok1 = n1 < NODES;
        const float* h0 = g_hm + (ok0 ? n0 : 0) * DIM;
        const float* h1 = g_hm + (ok1 ? n1 : 0) * DIM;

        float A[2][3], vn[2];
#pragma unroll
        for (int e = 0; e < 2; e++) {
            const float* h = e ? h1 : h0;
            float a0=0.f, a1=0.f, a2=0.f;
#pragma unroll
            for (int i = 0; i < 16; i++) {
                float wt = __ldg(&Wh4[i*32 + lane]);
                a0 = fmaf(h[3*i+0], wt, a0);
                a1 = fmaf(h[3*i+1], wt, a1);
                a2 = fmaf(h[3*i+2], wt, a2);
            }
            A[e][0]=a0; A[e][1]=a1; A[e][2]=a2;
            vn[e] = sqrtf(fmaf(a0,a0,fmaf(a1,a1,a2*a2)) + 1e-8f);
        }
        for (int t = lane; t < 100; t += 32) { xw[t] = h0[48+t]; xw[132+t] = h1[48+t]; }
        xw[100+lane] = vn[0]; xw[232+lane] = vn[1];
        __syncwarp();

        float acc0[13], acc1[13];
        int jm[13];
#pragma unroll
        for (int jj = 0; jj < 13; jj++) {
            int j = lane + jj*32; jm[jj] = j < 400 ? j : 399;
            float v = __ldg(&bs4[jm[jj]]);
            acc0[jj] = v; acc1[jj] = v;
        }
        const float4* x0 = (const float4*)xw;
        const float4* x1 = (const float4*)(xw + 132);
        for (int i4 = 0; i4 < 33; i4++) {
            float4 va = x0[i4], vb = x1[i4];
            const float* wr = sm + i4 * 1600;
#pragma unroll
            for (int q = 0; q < 4; q++) {
                float fa = f4c(va,q), fb = f4c(vb,q);
                const float* wq = wr + q * 400;
#pragma unroll
                for (int jj = 0; jj < 13; jj++) {
                    float wt = wq[jm[jj]];
                    acc0[jj] = fmaf(fa, wt, acc0[jj]);
                    acc1[jj] = fmaf(fb, wt, acc1[jj]);
                }
            }
        }
#pragma unroll
        for (int jj = 0; jj < 13; jj++) {
            acc0[jj] = fmaxf(acc0[jj], 0.f);
            acc1[jj] = fmaxf(acc1[jj], 0.f);
        }

#pragma unroll
        for (int e = 0; e < 2; e++) {
            float b0=0.f, b1=0.f, b2=0.f;
#pragma unroll
            for (int hh = 0; hh < 32; hh++) {
                float wt = __ldg(&Wv4[hh*32 + lane]);
                b0 = fmaf(__shfl_sync(0xffffffffu, A[e][0], hh), wt, b0);
                b1 = fmaf(__shfl_sync(0xffffffffu, A[e][1], hh), wt, b1);
                b2 = fmaf(__shfl_sync(0xffffffffu, A[e][2], hh), wt, b2);
            }
            float nr = sqrtf(fmaf(b0,b0,fmaf(b1,b1,b2*b2)) + 1e-8f);
            float gt = 1.f / (1.f + __expf(-nr));
            bool ok = e ? ok1 : ok0;
            long n = e ? n1 : n0;
            if (ok) {
                float* o = g_t4 + n * 496;
                o[3*lane+0]=b0*gt; o[3*lane+1]=b1*gt; o[3*lane+2]=b2*gt;
                float* acc = e ? acc1 : acc0;
#pragma unroll
                for (int jj = 0; jj < 13; jj++) {
                    int j = lane + jj*32;
                    if (j < 400) o[96+j] = acc[jj];
                }
            }
        }
        __syncwarp();
    }
}

// =================================================================
// Kernel 4: final
// =================================================================
#define F_W 43200
#define F_SMEM ((F_W + 8*864) * 4)

__global__ __launch_bounds__(256, 1)
void final_kernel(const int* __restrict__ maskV,
                  const float* __restrict__ Wh5, const float* __restrict__ Wv5,
                  const float* __restrict__ Ws5, const float* __restrict__ bs5,
                  const float* __restrict__ lng, const float* __restrict__ lnb,
                  float* __restrict__ out)
{
    extern __shared__ float sm[];
    const int tid = threadIdx.x, w = tid >> 5, lane = tid & 31;
    for (int i = tid; i < F_W; i += 256) sm[i] = __ldg(&Ws5[i]);
    __syncthreads();
    float* xw = sm + F_W + w * 864;

    for (long base = (long)blockIdx.x * 16; base < NODES; base += (long)gridDim.x * 16) {
        long n0 = base + w*2, n1 = n0 + 1;
        bool ok0 = n0 < NODES, ok1 = n1 < NODES;
        const float* t0 = g_t4 + (ok0 ? n0 : 0) * 496;
        const float* t1 = g_t4 + (ok1 ? n1 : 0) * 496;

        float A[2][3], vn[2];
#pragma unroll
        for (int e = 0; e < 2; e++) {
            const float* t = e ? t1 : t0;
            float a0=0.f, a1=0.f, a2=0.f;
#pragma unroll
            for (int i = 0; i < 32; i++) {
                float wt = __ldg(&Wh5[i*32 + lane]);
                a0 = fmaf(t[3*i+0], wt, a0);
                a1 = fmaf(t[3*i+1], wt, a1);
                a2 = fmaf(t[3*i+2], wt, a2);
            }
            A[e][0]=a0; A[e][1]=a1; A[e][2]=a2;
            vn[e] = sqrtf(fmaf(a0,a0,fmaf(a1,a1,a2*a2)) + 1e-8f);
        }
        for (int t = lane; t < 400; t += 32) { xw[t] = t0[96+t]; xw[432+t] = t1[96+t]; }
        xw[400+lane] = vn[0]; xw[832+lane] = vn[1];
        __syncwarp();

        float acc0[4], acc1[4];
        int jc[4];
#pragma unroll
        for (int jj = 0; jj < 4; jj++) {
            int j = jj*32 + lane; jc[jj] = j < 100 ? j : 99;
            float v = __ldg(&bs5[jc[jj]]);
            acc0[jj] = v; acc1[jj] = v;
        }
        const float4* x0 = (const float4*)xw;
        const float4* x1 = (const float4*)(xw + 432);
#pragma unroll 2
        for (int i4 = 0; i4 < 108; i4++) {
            float4 va = x0[i4], vb = x1[i4];
            const float* wr = sm + i4 * 400;
#pragma unroll
            for (int q = 0; q < 4; q++) {
                float fa = f4c(va,q), fb = f4c(vb,q);
                const float* wq = wr + q * 100;
#pragma unroll
                for (int jj = 0; jj < 4; jj++) {
                    float wt = wq[jc[jj]];
                    acc0[jj] = fmaf(fa, wt, acc0[jj]);
                    acc1[jj] = fmaf(fb, wt, acc1[jj]);
                }
            }
        }

        float Bv[2][3];
        const int lc = lane & 15;
#pragma unroll
        for (int e = 0; e < 2; e++) {
            float b0=0.f, b1=0.f, b2=0.f;
#pragma unroll
            for (int hh = 0; hh < 32; hh++) {
                float wt = __ldg(&Wv5[hh*16 + lc]);
                b0 = fmaf(__shfl_sync(0xffffffffu, A[e][0], hh), wt, b0);
                b1 = fmaf(__shfl_sync(0xffffffffu, A[e][1], hh), wt, b1);
                b2 = fmaf(__shfl_sync(0xffffffffu, A[e][2], hh), wt, b2);
            }
            Bv[e][0]=b0; Bv[e][1]=b1; Bv[e][2]=b2;
        }

#pragma unroll
        for (int e = 0; e < 2; e++) {
            bool ok = e ? ok1 : ok0;
            long n = e ? n1 : n0;
            const float* hm = g_hm + (ok ? n : 0) * DIM;
            const float* acc = e ? acc1 : acc0;

            float v0=0.f, v1=0.f, v2=0.f, q=0.f;
            if (lane < 16) {
                v0 = hm[3*lane+0] + Bv[e][0];
                v1 = hm[3*lane+1] + Bv[e][1];
                v2 = hm[3*lane+2] + Bv[e][2];
                q = fmaf(v0,v0,fmaf(v1,v1,v2*v2));
            }
#pragma unroll
            for (int o = 16; o; o >>= 1) q += __shfl_xor_sync(0xffffffffu, q, o);
            float dinv = rsqrtf(q * (1.f/16.f) + 1e-8f);

            float s[4]; float sum = 0.f, sq = 0.f;
#pragma unroll
            for (int jj = 0; jj < 4; jj++) {
                int j = jj*32 + lane;
                s[jj] = (j < 100) ? (hm[48+j] + acc[jj]) : 0.f;
                sum += s[jj]; sq = fmaf(s[jj], s[jj], sq);
            }
#pragma unroll
            for (int o = 16; o; o >>= 1) {
                sum += __shfl_xor_sync(0xffffffffu, sum, o);
                sq  += __shfl_xor_sync(0xffffffffu, sq,  o);
            }
            float mu  = sum * 0.01f;
            float var = sq * 0.01f - mu*mu;
            float inv = rsqrtf(var + 1e-5f);

            if (ok) {
                float m = (float)__ldg(&maskV[n]);
                float* o = out + n * DIM;
                if (lane < 16) {
                    o[3*lane+0] = m * v0 * dinv;
                    o[3*lane+1] = m * v1 * dinv;
                    o[3*lane+2] = m * v2 * dinv;
                }
#pragma unroll
                for (int jj = 0; jj < 4; jj++) {
                    int j = jj*32 + lane;
                    if (j < 100)
                        o[48+j] = m * ((s[jj]-mu)*inv*__ldg(&lng[j]) + __ldg(&lnb[j]));
                }
            }
        }
        __syncwarp();
    }
}

// =================================================================
extern "C" void kernel_launch(void* const* d_in, const int* in_sizes, int n_in,
                              void* d_out, int out_size)
{
    const float* hV    = (const float*)d_in[0];
    const float* hM    = (const float*)d_in[1];
    const int*   maskV = (const int*)  d_in[2];
    const int*   maskA = (const int*)  d_in[3];
    const float* Wh1 = (const float*)d_in[4];
    const float* Wv1 = (const float*)d_in[5];
    const float* Ws1 = (const float*)d_in[6];
    const float* bs1 = (const float*)d_in[7];
    const float* Wh2 = (const float*)d_in[8];
    const float* Wv2 = (const float*)d_in[9];
    const float* Ws2 = (const float*)d_in[10];
    const float* bs2 = (const float*)d_in[11];
    const float* Wh3 = (const float*)d_in[12];
    const float* Wv3 = (const float*)d_in[13];
    const float* Ws3 = (const float*)d_in[14];
    const float* bs3 = (const float*)d_in[15];
    const float* Wh4 = (const float*)d_in[16];
    const float* Wv4 = (const float*)d_in[17];
    const float* Ws4 = (const float*)d_in[18];
    const float* bs4 = (const float*)d_in[19];
    const float* Wh5 = (const float*)d_in[20];
    const float* Wv5 = (const float*)d_in[21];
    const float* Ws5 = (const float*)d_in[22];
    const float* bs5 = (const float*)d_in[23];
    const float* ln0g = (const float*)d_in[24];
    const float* ln0b = (const float*)d_in[25];
    const float* ln1g = (const float*)d_in[26];
    const float* ln1b = (const float*)d_in[27];

    static int attr_done = 0;
    if (!attr_done) {
        cudaFuncSetAttribute(pre_kernel,
                             cudaFuncAttributeMaxDynamicSharedMemorySize, PRE_SMEM);
        cudaFuncSetAttribute(edge_kernel,
                             cudaFuncAttributeMaxDynamicSharedMemorySize, EDGE_SMEM);
        cudaFuncSetAttribute(gvp4_kernel,
                             cudaFuncAttributeMaxDynamicSharedMemorySize, G4_SMEM);
        cudaFuncSetAttribute(final_kernel,
                             cudaFuncAttributeMaxDynamicSharedMemorySize, F_SMEM);
        attr_done = 1;
    }

    pre_kernel <<<148, 256, PRE_SMEM >>>(hV, Wh1, Ws1, bs1);
    edge_kernel<<<148, 512, EDGE_SMEM>>>(hM, maskA, hV, ln0g, ln0b,
                                         Wh1, Wv1, Ws1,
                                         Wh2, Wv2, Ws2, bs2,
                                         Wh3, Wv3, Ws3, bs3);
    gvp4_kernel<<<148, 256, G4_SMEM>>>(Wh4, Wv4, Ws4, bs4);
    final_kernel<<<148, 256, F_SMEM>>>(maskV, Wh5, Wv5, Ws5, bs5, ln1g, ln1b,
                                       (float*)d_out);
}